// round 1
// baseline (speedup 1.0000x reference)
#include <cuda_runtime.h>
#include <math.h>
#include <stdint.h>

#define NN   2048
#define DD   512
#define HH   8
#define HDIM 64
#define DPEC 16
#define WALKC 8
#define LLC  3
#define EEC  32768
#define DFFC 2048
#define MAXD 256

// ---------------- static device scratch (no runtime allocation) ----------------
__device__ float g_T [NN*NN];   // adjacency -> row-normalized T (in place)
__device__ float g_T2[NN*NN];
__device__ float g_T3[NN*NN];
__device__ float g_T4[NN*NN];
__device__ float g_deg[NN];
__device__ float g_invdeg[NN];
__device__ int   g_nbr[NN*MAXD];
__device__ int   g_cnt[NN];
__device__ float g_rw [NN*WALKC];
__device__ float g_pe [NN*DPEC];
__device__ float g_pep[LLC*NN*HH];
__device__ float g_x   [NN*DD];
__device__ float g_x1  [NN*DD];
__device__ float g_qkv [NN*3*DD];
__device__ float g_attn[NN*DD];
__device__ float g_o   [NN*DD];
__device__ float g_h   [NN*DFFC];

// ---------------- PE pipeline ----------------

__global__ void zero_T_kernel() {
    size_t idx = (size_t)blockIdx.x * blockDim.x + threadIdx.x;   // 4096*256 threads, 4 floats each
    float4* p = reinterpret_cast<float4*>(g_T);
    if (idx * 4 < (size_t)NN * NN) p[idx] = make_float4(0.f, 0.f, 0.f, 0.f);
}

__global__ void scatter_kernel(const int* __restrict__ ei) {
    int e = blockIdx.x * blockDim.x + threadIdx.x;
    if (e < EEC) {
        int s = ei[e];
        int t = ei[EEC + e];
        g_T[(size_t)s * NN + t] = 1.f;
        g_T[(size_t)t * NN + s] = 1.f;
    }
}

__global__ void deg_kernel() {
    __shared__ float sh[256];
    int i = blockIdx.x, t = threadIdx.x;
    float s = 0.f;
    const float* row = g_T + (size_t)i * NN;
    for (int j = t; j < NN; j += 256) s += row[j];
    sh[t] = s; __syncthreads();
    for (int k = 128; k > 0; k >>= 1) { if (t < k) sh[t] += sh[t + k]; __syncthreads(); }
    if (t == 0) {
        float d = sh[0] < 1.f ? 1.f : sh[0];
        g_deg[i] = d;
        g_invdeg[i] = 1.f / d;
    }
}

__global__ void buildT_kernel() {
    __shared__ int cnt;
    int i = blockIdx.x, t = threadIdx.x;
    if (t == 0) cnt = 0;
    __syncthreads();
    float inv = g_invdeg[i];
    float* row = g_T + (size_t)i * NN;
    for (int j = t; j < NN; j += 256) {
        float a = row[j];
        if (a != 0.f) {
            int p = atomicAdd(&cnt, 1);
            if (p < MAXD) g_nbr[i * MAXD + p] = j;
            row[j] = a * inv;
        }
    }
    __syncthreads();
    if (t == 0) g_cnt[i] = cnt < MAXD ? cnt : MAXD;
}

// OUT[i,:] = invdeg_i * sum_{j in nbr(i)} IN[j,:]   (i.e. OUT = T @ IN)
__global__ void __launch_bounds__(256) spmm_kernel(const float* __restrict__ IN, float* __restrict__ OUT) {
    int i = blockIdx.x, t = threadIdx.x;
    int cnt = g_cnt[i];
    float inv = g_invdeg[i];
    const int* nb = g_nbr + i * MAXD;
    float acc[8] = {0.f,0.f,0.f,0.f,0.f,0.f,0.f,0.f};
    for (int c = 0; c < cnt; c++) {
        const float* row = IN + (size_t)nb[c] * NN;
        #pragma unroll
        for (int u = 0; u < 8; u++) acc[u] += row[t + u * 256];
    }
    float* out = OUT + (size_t)i * NN;
    #pragma unroll
    for (int u = 0; u < 8; u++) out[t + u * 256] = acc[u] * inv;
}

// diag(T^(a+b))_i = d_i * sum_j (T^a)_ij (T^b)_ij / d_j
__global__ void diag_kernel() {
    __shared__ float sh[256];
    __shared__ float res[7];
    int i = blockIdx.x, t = threadIdx.x;
    const float* r1 = g_T  + (size_t)i * NN;
    const float* r2 = g_T2 + (size_t)i * NN;
    const float* r3 = g_T3 + (size_t)i * NN;
    const float* r4 = g_T4 + (size_t)i * NN;
    float s[7] = {0.f,0.f,0.f,0.f,0.f,0.f,0.f};
    for (int j = t; j < NN; j += 256) {
        float w = g_invdeg[j];
        float a = r1[j], b = r2[j], c = r3[j], d = r4[j];
        s[0] += a * a * w;   // diag T^2
        s[1] += b * a * w;   // diag T^3
        s[2] += b * b * w;   // diag T^4
        s[3] += c * b * w;   // diag T^5
        s[4] += c * c * w;   // diag T^6
        s[5] += d * c * w;   // diag T^7
        s[6] += d * d * w;   // diag T^8
    }
    for (int v = 0; v < 7; v++) {
        sh[t] = s[v]; __syncthreads();
        for (int k = 128; k > 0; k >>= 1) { if (t < k) sh[t] += sh[t + k]; __syncthreads(); }
        if (t == 0) res[v] = sh[0];
        __syncthreads();
    }
    if (t == 0) {
        float di = g_deg[i];
        g_rw[i * WALKC + 0] = r1[i];           // diag T^1
        #pragma unroll
        for (int v = 0; v < 7; v++) g_rw[i * WALKC + 1 + v] = res[v] * di;
    }
}

__global__ void pe_kernel(const float* __restrict__ W, const float* __restrict__ b) {
    int i = blockIdx.x * blockDim.x + threadIdx.x;
    if (i >= NN) return;
    float r[WALKC];
    #pragma unroll
    for (int w = 0; w < WALKC; w++) r[w] = g_rw[i * WALKC + w];
    #pragma unroll
    for (int d = 0; d < DPEC; d++) {
        float s = b[d];
        #pragma unroll
        for (int w = 0; w < WALKC; w++) s += r[w] * W[w * DPEC + d];
        g_pe[i * DPEC + d] = s;
    }
}

__global__ void pep_kernel(const float* __restrict__ W, const float* __restrict__ b) {
    int i = blockIdx.x * blockDim.x + threadIdx.x;
    if (i >= NN) return;
    float p[DPEC];
    #pragma unroll
    for (int d = 0; d < DPEC; d++) p[d] = g_pe[i * DPEC + d];
    for (int l = 0; l < LLC; l++) {
        #pragma unroll
        for (int h = 0; h < HH; h++) {
            float s = b[l * HH + h];
            #pragma unroll
            for (int d = 0; d < DPEC; d++) s += p[d] * W[(l * DPEC + d) * HH + h];
            g_pep[(size_t)l * NN * HH + i * HH + h] = s;
        }
    }
}

// ---------------- dense fp32 GEMM: C = A@B + bias (optional exact GELU) ----------------
// 128x128 tile, BK=8, 256 threads, 8x8 microtile.  M,Nd,K all multiples of 128/8 here.
template<int EPI>
__global__ void __launch_bounds__(256) gemm_kernel(const float* __restrict__ A, const float* __restrict__ B,
                                                   const float* __restrict__ bias, float* __restrict__ C,
                                                   int M, int Nd, int K) {
    __shared__ float As[8][128];
    __shared__ float Bs[8][128];
    const int tid  = threadIdx.x;
    const int brow = blockIdx.y, bcol = blockIdx.x;
    const int arow = tid >> 1, acol = (tid & 1) << 2;
    const int brw  = tid >> 5, bcl  = (tid & 31) << 2;
    const int tx = (tid & 15) << 3;
    const int ty = (tid >> 4) << 3;
    const float* Ap = A + (size_t)(brow * 128 + arow) * K + acol;
    const float* Bp = B + (size_t)brw * Nd + bcol * 128 + bcl;
    float acc[8][8] = {};
    for (int k0 = 0; k0 < K; k0 += 8) {
        float4 av = *(const float4*)(Ap + k0);
        float4 bv = *(const float4*)(Bp + (size_t)k0 * Nd);
        As[acol + 0][arow] = av.x; As[acol + 1][arow] = av.y;
        As[acol + 2][arow] = av.z; As[acol + 3][arow] = av.w;
        *(float4*)&Bs[brw][bcl] = bv;
        __syncthreads();
        #pragma unroll
        for (int kk = 0; kk < 8; kk++) {
            float ra[8], rb[8];
            *(float4*)(ra)     = *(const float4*)&As[kk][ty];
            *(float4*)(ra + 4) = *(const float4*)&As[kk][ty + 4];
            *(float4*)(rb)     = *(const float4*)&Bs[kk][tx];
            *(float4*)(rb + 4) = *(const float4*)&Bs[kk][tx + 4];
            #pragma unroll
            for (int i = 0; i < 8; i++)
                #pragma unroll
                for (int j = 0; j < 8; j++)
                    acc[i][j] += ra[i] * rb[j];
        }
        __syncthreads();
    }
    #pragma unroll
    for (int i = 0; i < 8; i++) {
        float* Cp = C + (size_t)(brow * 128 + ty + i) * Nd + bcol * 128 + tx;
        #pragma unroll
        for (int j = 0; j < 8; j++) {
            float v = acc[i][j] + bias[bcol * 128 + tx + j];
            if (EPI == 1) v = 0.5f * v * (1.f + erff(v * 0.70710678118654752f));
            Cp[j] = v;
        }
    }
}

// ---------------- fused attention ----------------
// scores(i,j) = (q_i * scale) . k_j - pep[j,h]   (row-constant +pep[i,h] cancels in softmax)
// Scores are provably small (|s| < ~32) so fixed max m=0 is numerically safe.
__global__ void __launch_bounds__(64) attn_kernel(const float* __restrict__ qkv,
                                                  const float* __restrict__ pep,
                                                  float* __restrict__ out) {
    const int h  = blockIdx.y;
    const int q0 = blockIdx.x * 64;
    const int t  = threadIdx.x;
    __shared__ float Ks[64][64];
    __shared__ float Vs[64][64];
    __shared__ float bs[64];
    const int i = q0 + t;
    const float* qp = qkv + (size_t)i * 1536 + h * 64;
    float q[64];
    #pragma unroll
    for (int d = 0; d < 64; d++) q[d] = qp[d] * 0.125f;   // HD^-0.5 = 1/8
    float acc[64];
    #pragma unroll
    for (int d = 0; d < 64; d++) acc[d] = 0.f;
    float lsum = 0.f;
    for (int j0 = 0; j0 < NN; j0 += 64) {
        __syncthreads();
        for (int x = t; x < 64 * 64; x += 64) {
            int j = x >> 6, d = x & 63;
            Ks[j][d] = qkv[(size_t)(j0 + j) * 1536 + 512  + h * 64 + d];
            Vs[j][d] = qkv[(size_t)(j0 + j) * 1536 + 1024 + h * 64 + d];
        }
        bs[t] = pep[(size_t)(j0 + t) * HH + h];
        __syncthreads();
        #pragma unroll 1
        for (int j = 0; j < 64; j++) {
            const float4* kr = reinterpret_cast<const float4*>(&Ks[j][0]);
            float s = -bs[j];
            #pragma unroll
            for (int d4 = 0; d4 < 16; d4++) {
                float4 kv = kr[d4];
                s += q[d4*4+0]*kv.x + q[d4*4+1]*kv.y + q[d4*4+2]*kv.z + q[d4*4+3]*kv.w;
            }
            float p = __expf(s);
            lsum += p;
            const float4* vr = reinterpret_cast<const float4*>(&Vs[j][0]);
            #pragma unroll
            for (int d4 = 0; d4 < 16; d4++) {
                float4 vv = vr[d4];
                acc[d4*4+0] += p * vv.x; acc[d4*4+1] += p * vv.y;
                acc[d4*4+2] += p * vv.z; acc[d4*4+3] += p * vv.w;
            }
        }
    }
    float invl = 1.f / lsum;
    float* op = out + (size_t)i * DD + h * 64;
    #pragma unroll
    for (int d = 0; d < 64; d++) op[d] = acc[d] * invl;
}

// ---------------- misc ----------------
__global__ void copy_x_kernel(const float* __restrict__ src) {
    size_t idx = (size_t)blockIdx.x * blockDim.x + threadIdx.x;
    float4* dst = reinterpret_cast<float4*>(g_x);
    const float4* s4 = reinterpret_cast<const float4*>(src);
    if (idx * 4 < (size_t)NN * DD) dst[idx] = s4[idx];
}

// out[i,:] = LN(a[i,:] + b[i,:]) * g + beta
__global__ void ln_kernel(const float* __restrict__ a, const float* __restrict__ b,
                          const float* __restrict__ g, const float* __restrict__ be,
                          float* __restrict__ out) {
    __shared__ float sh[256];
    __shared__ float s_mu, s_r;
    int i = blockIdx.x, t = threadIdx.x;
    float v0 = a[(size_t)i * DD + t]       + b[(size_t)i * DD + t];
    float v1 = a[(size_t)i * DD + 256 + t] + b[(size_t)i * DD + 256 + t];
    sh[t] = v0 + v1; __syncthreads();
    for (int k = 128; k > 0; k >>= 1) { if (t < k) sh[t] += sh[t + k]; __syncthreads(); }
    if (t == 0) s_mu = sh[0] * (1.f / DD);
    __syncthreads();
    float mu = s_mu;
    float d0 = v0 - mu, d1 = v1 - mu;
    sh[t] = d0 * d0 + d1 * d1; __syncthreads();
    for (int k = 128; k > 0; k >>= 1) { if (t < k) sh[t] += sh[t + k]; __syncthreads(); }
    if (t == 0) s_r = rsqrtf(sh[0] * (1.f / DD) + 1e-5f);
    __syncthreads();
    float r = s_r;
    out[(size_t)i * DD + t]       = d0 * r * g[t]       + be[t];
    out[(size_t)i * DD + 256 + t] = d1 * r * g[256 + t] + be[256 + t];
}

// ---------------- launch ----------------
extern "C" void kernel_launch(void* const* d_in, const int* in_sizes, int n_in,
                              void* d_out, int out_size) {
    const float* node_features = (const float*)d_in[0];
    const int*   edge_index    = (const int*)  d_in[1];
    const float* pe_proj_W     = (const float*)d_in[2];
    const float* pe_proj_b     = (const float*)d_in[3];
    const float* qkv_W         = (const float*)d_in[4];
    const float* qkv_b         = (const float*)d_in[5];
    const float* peb_W         = (const float*)d_in[6];
    const float* peb_b         = (const float*)d_in[7];
    const float* out_W         = (const float*)d_in[8];
    const float* out_b         = (const float*)d_in[9];
    const float* ffn_W1        = (const float*)d_in[10];
    const float* ffn_b1        = (const float*)d_in[11];
    const float* ffn_W2        = (const float*)d_in[12];
    const float* ffn_b2        = (const float*)d_in[13];
    const float* ln1_g         = (const float*)d_in[14];
    const float* ln1_b         = (const float*)d_in[15];
    const float* ln2_g         = (const float*)d_in[16];
    const float* ln2_b         = (const float*)d_in[17];
    float* outp = (float*)d_out;

    float *T_, *T2_, *T3_, *T4_, *x_, *x1_, *qkv_, *attn_, *o_, *h_, *pep_;
    cudaGetSymbolAddress((void**)&T_,   g_T);
    cudaGetSymbolAddress((void**)&T2_,  g_T2);
    cudaGetSymbolAddress((void**)&T3_,  g_T3);
    cudaGetSymbolAddress((void**)&T4_,  g_T4);
    cudaGetSymbolAddress((void**)&x_,   g_x);
    cudaGetSymbolAddress((void**)&x1_,  g_x1);
    cudaGetSymbolAddress((void**)&qkv_, g_qkv);
    cudaGetSymbolAddress((void**)&attn_,g_attn);
    cudaGetSymbolAddress((void**)&o_,   g_o);
    cudaGetSymbolAddress((void**)&h_,   g_h);
    cudaGetSymbolAddress((void**)&pep_, g_pep);

    // ---- PE pipeline ----
    zero_T_kernel<<<4096, 256>>>();
    scatter_kernel<<<EEC / 256, 256>>>(edge_index);
    deg_kernel<<<NN, 256>>>();
    buildT_kernel<<<NN, 256>>>();
    spmm_kernel<<<NN, 256>>>(T_,  T2_);
    spmm_kernel<<<NN, 256>>>(T2_, T3_);
    spmm_kernel<<<NN, 256>>>(T3_, T4_);
    diag_kernel<<<NN, 256>>>();
    pe_kernel<<<(NN + 127) / 128, 128>>>(pe_proj_W, pe_proj_b);
    pep_kernel<<<(NN + 127) / 128, 128>>>(peb_W, peb_b);

    // ---- transformer ----
    copy_x_kernel<<<1024, 256>>>(node_features);
    for (int l = 0; l < LLC; l++) {
        gemm_kernel<0><<<dim3(1536/128, NN/128), 256>>>(x_, qkv_W + (size_t)l*DD*3*DD,
                                                        qkv_b + (size_t)l*3*DD, qkv_, NN, 3*DD, DD);
        attn_kernel<<<dim3(NN/64, HH), 64>>>(qkv_, pep_ + (size_t)l*NN*HH, attn_);
        gemm_kernel<0><<<dim3(DD/128, NN/128), 256>>>(attn_, out_W + (size_t)l*DD*DD,
                                                      out_b + (size_t)l*DD, o_, NN, DD, DD);
        ln_kernel<<<NN, 256>>>(x_, o_, ln1_g + (size_t)l*DD, ln1_b + (size_t)l*DD, x1_);
        gemm_kernel<1><<<dim3(DFFC/128, NN/128), 256>>>(x1_, ffn_W1 + (size_t)l*DD*DFFC,
                                                        ffn_b1 + (size_t)l*DFFC, h_, NN, DFFC, DD);
        gemm_kernel<0><<<dim3(DD/128, NN/128), 256>>>(h_, ffn_W2 + (size_t)l*DFFC*DD,
                                                      ffn_b2 + (size_t)l*DD, o_, NN, DD, DFFC);
        float* xout = (l == LLC - 1) ? outp : x_;
        ln_kernel<<<NN, 256>>>(x1_, o_, ln2_g + (size_t)l*DD, ln2_b + (size_t)l*DD, xout);
    }
}

// round 3
// speedup vs baseline: 1.9373x; 1.9373x over previous
#include <cuda_runtime.h>
#include <cuda_bf16.h>
#include <math.h>
#include <stdint.h>

#define NN   2048
#define DD   512
#define HH   8
#define DPEC 16
#define WALKC 8
#define LLC  3
#define EEC  32768
#define DFFC 2048
#define MAXD 256

// ============================ PTX helpers (baseline ISA only: sm_80-safe) ============================
__device__ __forceinline__ uint32_t smem_to_u32(const void* p) {
    uint32_t a;
    asm("{ .reg .u64 t; cvta.to.shared.u64 t, %1; cvt.u32.u64 %0, t; }" : "=r"(a) : "l"(p));
    return a;
}
#define CP_ASYNC16(dst, src) \
    asm volatile("cp.async.cg.shared.global [%0], [%1], 16;" :: "r"(dst), "l"(src))
#define CP_COMMIT() asm volatile("cp.async.commit_group;" ::: "memory")
#define CP_WAIT1()  asm volatile("cp.async.wait_group 1;" ::: "memory")
#define CP_WAIT0()  asm volatile("cp.async.wait_group 0;" ::: "memory")

__device__ __forceinline__ void ldsm4(uint32_t* r, uint32_t addr) {
    asm volatile("ldmatrix.sync.aligned.m8n8.x4.shared.b16 {%0,%1,%2,%3}, [%4];"
        : "=r"(r[0]), "=r"(r[1]), "=r"(r[2]), "=r"(r[3]) : "r"(addr));
}
__device__ __forceinline__ void mma16816(float* c, const uint32_t* a, const uint32_t* b) {
    asm volatile("mma.sync.aligned.m16n8k16.row.col.f32.bf16.bf16.f32 "
        "{%0,%1,%2,%3}, {%4,%5,%6,%7}, {%8,%9}, {%0,%1,%2,%3};"
        : "+f"(c[0]), "+f"(c[1]), "+f"(c[2]), "+f"(c[3])
        : "r"(a[0]), "r"(a[1]), "r"(a[2]), "r"(a[3]), "r"(b[0]), "r"(b[1]));
}

// ============================ static device scratch ============================
__device__ float g_T [NN*NN];
__device__ float g_T2[NN*NN];
__device__ float g_T3[NN*NN];
__device__ float g_T4[NN*NN];
__device__ float g_deg[NN];
__device__ float g_invdeg[NN];
__device__ int   g_nbr[NN*MAXD];
__device__ int   g_cnt[NN];
__device__ float g_rw [NN*WALKC];
__device__ float g_pe [NN*DPEC];
__device__ float g_pep[LLC*NN*HH];
__device__ float g_x   [NN*DD];
__device__ float g_x1  [NN*DD];
__device__ float g_qkv [NN*3*DD];
__device__ float g_attn[NN*DD];
__device__ float g_o   [NN*DD];
__device__ float g_h   [NN*DFFC];
// bf16 split scratch
__device__ __nv_bfloat16 g_Ahi[NN*DFFC];
__device__ __nv_bfloat16 g_Alo[NN*DFFC];
__device__ __nv_bfloat16 g_qkvW_hi[LLC*3*DD*DD];
__device__ __nv_bfloat16 g_qkvW_lo[LLC*3*DD*DD];
__device__ __nv_bfloat16 g_outW_hi[LLC*DD*DD];
__device__ __nv_bfloat16 g_outW_lo[LLC*DD*DD];
__device__ __nv_bfloat16 g_f1W_hi[LLC*DD*DFFC];
__device__ __nv_bfloat16 g_f1W_lo[LLC*DD*DFFC];
__device__ __nv_bfloat16 g_f2W_hi[LLC*DFFC*DD];
__device__ __nv_bfloat16 g_f2W_lo[LLC*DFFC*DD];
// attention partials
__device__ float g_part [4*HH*NN*64];
__device__ float g_plsum[4*HH*NN];

// ============================ PE pipeline ============================
__global__ void zero_T_kernel() {
    size_t idx = (size_t)blockIdx.x * blockDim.x + threadIdx.x;
    float4* p = reinterpret_cast<float4*>(g_T);
    if (idx * 4 < (size_t)NN * NN) p[idx] = make_float4(0.f, 0.f, 0.f, 0.f);
}
__global__ void scatter_kernel(const int* __restrict__ ei) {
    int e = blockIdx.x * blockDim.x + threadIdx.x;
    if (e < EEC) {
        int s = ei[e], t = ei[EEC + e];
        g_T[(size_t)s * NN + t] = 1.f;
        g_T[(size_t)t * NN + s] = 1.f;
    }
}
__global__ void deg_kernel() {
    __shared__ float sh[256];
    int i = blockIdx.x, t = threadIdx.x;
    float s = 0.f;
    const float* row = g_T + (size_t)i * NN;
    for (int j = t; j < NN; j += 256) s += row[j];
    sh[t] = s; __syncthreads();
    for (int k = 128; k > 0; k >>= 1) { if (t < k) sh[t] += sh[t + k]; __syncthreads(); }
    if (t == 0) {
        float d = sh[0] < 1.f ? 1.f : sh[0];
        g_deg[i] = d; g_invdeg[i] = 1.f / d;
    }
}
__global__ void buildT_kernel() {
    __shared__ int cnt;
    int i = blockIdx.x, t = threadIdx.x;
    if (t == 0) cnt = 0;
    __syncthreads();
    float inv = g_invdeg[i];
    float* row = g_T + (size_t)i * NN;
    for (int j = t; j < NN; j += 256) {
        float a = row[j];
        if (a != 0.f) {
            int p = atomicAdd(&cnt, 1);
            if (p < MAXD) g_nbr[i * MAXD + p] = j;
            row[j] = a * inv;
        }
    }
    __syncthreads();
    if (t == 0) g_cnt[i] = cnt < MAXD ? cnt : MAXD;
}
__global__ void __launch_bounds__(256) spmm_kernel(const float* __restrict__ IN, float* __restrict__ OUT) {
    int i = blockIdx.x, t = threadIdx.x;
    int cnt = g_cnt[i];
    float inv = g_invdeg[i];
    const int* nb = g_nbr + i * MAXD;
    float acc[8] = {};
    for (int c = 0; c < cnt; c++) {
        const float* row = IN + (size_t)nb[c] * NN;
        #pragma unroll
        for (int u = 0; u < 8; u++) acc[u] += row[t + u * 256];
    }
    float* out = OUT + (size_t)i * NN;
    #pragma unroll
    for (int u = 0; u < 8; u++) out[t + u * 256] = acc[u] * inv;
}
__global__ void diag_kernel() {
    __shared__ float sh[256];
    __shared__ float res[7];
    int i = blockIdx.x, t = threadIdx.x;
    const float* r1 = g_T  + (size_t)i * NN;
    const float* r2 = g_T2 + (size_t)i * NN;
    const float* r3 = g_T3 + (size_t)i * NN;
    const float* r4 = g_T4 + (size_t)i * NN;
    float s[7] = {};
    for (int j = t; j < NN; j += 256) {
        float w = g_invdeg[j];
        float a = r1[j], b = r2[j], c = r3[j], d = r4[j];
        s[0] += a * a * w; s[1] += b * a * w; s[2] += b * b * w;
        s[3] += c * b * w; s[4] += c * c * w; s[5] += d * c * w; s[6] += d * d * w;
    }
    for (int v = 0; v < 7; v++) {
        sh[t] = s[v]; __syncthreads();
        for (int k = 128; k > 0; k >>= 1) { if (t < k) sh[t] += sh[t + k]; __syncthreads(); }
        if (t == 0) res[v] = sh[0];
        __syncthreads();
    }
    if (t == 0) {
        float di = g_deg[i];
        g_rw[i * WALKC + 0] = r1[i];
        #pragma unroll
        for (int v = 0; v < 7; v++) g_rw[i * WALKC + 1 + v] = res[v] * di;
    }
}
__global__ void pe_kernel(const float* __restrict__ W, const float* __restrict__ b) {
    int i = blockIdx.x * blockDim.x + threadIdx.x;
    if (i >= NN) return;
    float r[WALKC];
    #pragma unroll
    for (int w = 0; w < WALKC; w++) r[w] = g_rw[i * WALKC + w];
    #pragma unroll
    for (int d = 0; d < DPEC; d++) {
        float s = b[d];
        #pragma unroll
        for (int w = 0; w < WALKC; w++) s += r[w] * W[w * DPEC + d];
        g_pe[i * DPEC + d] = s;
    }
}
__global__ void pep_kernel(const float* __restrict__ W, const float* __restrict__ b) {
    int i = blockIdx.x * blockDim.x + threadIdx.x;
    if (i >= NN) return;
    float p[DPEC];
    #pragma unroll
    for (int d = 0; d < DPEC; d++) p[d] = g_pe[i * DPEC + d];
    for (int l = 0; l < LLC; l++) {
        #pragma unroll
        for (int h = 0; h < HH; h++) {
            float s = b[l * HH + h];
            #pragma unroll
            for (int d = 0; d < DPEC; d++) s += p[d] * W[(l * DPEC + d) * HH + h];
            g_pep[(size_t)l * NN * HH + i * HH + h] = s;
        }
    }
}

// ============================ fp32 -> bf16 hi/lo conversion ============================
__global__ void splitA_kernel(const float* __restrict__ a, __nv_bfloat16* __restrict__ hi,
                              __nv_bfloat16* __restrict__ lo, int n) {
    int idx = blockIdx.x * blockDim.x + threadIdx.x;
    for (int i = idx; i < n; i += gridDim.x * blockDim.x) {
        float v = a[i];
        __nv_bfloat16 h = __float2bfloat16_rn(v);
        hi[i] = h;
        lo[i] = __float2bfloat16_rn(v - __bfloat162float(h));
    }
}
// Weight transpose+split: W [K,N] fp32 -> hi/lo [N,K] bf16
__global__ void convW_kernel(const float* __restrict__ W, __nv_bfloat16* __restrict__ hi,
                             __nv_bfloat16* __restrict__ lo, int K, int N) {
    __shared__ float tile[32][33];
    int n0 = blockIdx.x * 32, k0 = blockIdx.y * 32;
    int tx = threadIdx.x, ty = threadIdx.y;   // block (32,8)
    #pragma unroll
    for (int r = 0; r < 4; r++)
        tile[ty + r * 8][tx] = W[(size_t)(k0 + ty + r * 8) * N + n0 + tx];
    __syncthreads();
    #pragma unroll
    for (int r = 0; r < 4; r++) {
        int ni = ty + r * 8;
        float v = tile[tx][ni];
        __nv_bfloat16 h = __float2bfloat16_rn(v);
        size_t o = (size_t)(n0 + ni) * K + k0 + tx;
        hi[o] = h;
        lo[o] = __float2bfloat16_rn(v - __bfloat162float(h));
    }
}

// ============================ mma.sync bf16x3 GEMM ============================
// C[M,N] = A[M,K] @ B^T + bias, B stored [N,K]; A,B as bf16 hi/lo pairs.
// CTA tile 128x128, BK=64, 256 threads (8 warps in 4x2; warp tile 32x64).
// smem rows = 128 bytes (64 bf16); 16B-chunk XOR swizzle: c' = c ^ (row&7).
// Double-buffered cp.async.
#define GSTAGE 65536
#define GSMEM_TOTAL (2 * GSTAGE)

template<int EPI>
__global__ void __launch_bounds__(256) mma_gemm_kernel(
    const __nv_bfloat16* __restrict__ Ahi, const __nv_bfloat16* __restrict__ Alo,
    const __nv_bfloat16* __restrict__ Bhi, const __nv_bfloat16* __restrict__ Blo,
    const float* __restrict__ bias, float* __restrict__ C, int N, int K)
{
    extern __shared__ char smem[];
    const int tid  = threadIdx.x;
    const int lane = tid & 31;
    const int wid  = tid >> 5;
    const int m0 = blockIdx.y * 128, n0 = blockIdx.x * 128;
    const int wrow = (wid >> 1) * 32;   // warp M offset in tile
    const int wcol = (wid & 1) * 64;    // warp N offset in tile
    const uint32_t sbase = smem_to_u32(smem);

    float acc[2][8][4];
    #pragma unroll
    for (int a = 0; a < 2; a++)
        #pragma unroll
        for (int b = 0; b < 8; b++)
            #pragma unroll
            for (int c = 0; c < 4; c++) acc[a][b][c] = 0.f;

    const int nc = K >> 6;

    auto loadChunk = [&](int c) {
        uint32_t sb = sbase + (uint32_t)(c & 1) * GSTAGE;
        int k0 = c << 6;
        #pragma unroll
        for (int t4 = 0; t4 < 4; t4++) {
            const __nv_bfloat16* s = (t4 == 0) ? Ahi : (t4 == 1) ? Alo : (t4 == 2) ? Bhi : Blo;
            int r0 = (t4 < 2) ? m0 : n0;
            #pragma unroll
            for (int it = 0; it < 4; it++) {
                int idx = it * 256 + tid;
                int row = idx >> 3, ch = idx & 7;
                const void* src = s + (size_t)(r0 + row) * K + k0 + ch * 8;
                uint32_t dst = sb + t4 * 16384 + row * 128 + ((ch ^ (row & 7)) << 4);
                CP_ASYNC16(dst, src);
            }
        }
        CP_COMMIT();
    };

    loadChunk(0);
    if (nc > 1) loadChunk(1);

    for (int c = 0; c < nc; c++) {
        if (c + 1 < nc) CP_WAIT1(); else CP_WAIT0();
        __syncthreads();
        uint32_t sb = sbase + (uint32_t)(c & 1) * GSTAGE;
        uint32_t sAh = sb, sAl = sb + 16384, sBh = sb + 32768, sBl = sb + 49152;
        #pragma unroll
        for (int ks = 0; ks < 4; ks++) {
            uint32_t ah[2][4], al[2][4], bh[4][4], bl[4][4];
            {   // A fragments (16x16 per mblock)
                int sub = lane >> 3;
                int row16 = (lane & 7) + ((sub & 1) << 3);
                int kc = ks * 2 + (sub >> 1);
                #pragma unroll
                for (int mb = 0; mb < 2; mb++) {
                    int row = wrow + mb * 16 + row16;
                    uint32_t off = (uint32_t)(row * 128 + ((kc ^ (row & 7)) << 4));
                    ldsm4(ah[mb], sAh + off);
                    ldsm4(al[mb], sAl + off);
                }
            }
            {   // B fragments (2 n8-blocks per x4)
                int sub = lane >> 3;
                int kc = ks * 2 + (sub & 1);
                int nr = ((sub >> 1) << 3) + (lane & 7);
                #pragma unroll
                for (int j = 0; j < 4; j++) {
                    int row = wcol + j * 16 + nr;
                    uint32_t off = (uint32_t)(row * 128 + ((kc ^ (row & 7)) << 4));
                    ldsm4(bh[j], sBh + off);
                    ldsm4(bl[j], sBl + off);
                }
            }
            #pragma unroll
            for (int mb = 0; mb < 2; mb++)
                #pragma unroll
                for (int j = 0; j < 4; j++) {
                    mma16816(acc[mb][2*j],     ah[mb], &bh[j][0]);
                    mma16816(acc[mb][2*j],     ah[mb], &bl[j][0]);
                    mma16816(acc[mb][2*j],     al[mb], &bh[j][0]);
                    mma16816(acc[mb][2*j + 1], ah[mb], &bh[j][2]);
                    mma16816(acc[mb][2*j + 1], ah[mb], &bl[j][2]);
                    mma16816(acc[mb][2*j + 1], al[mb], &bh[j][2]);
                }
        }
        __syncthreads();
        if (c + 2 < nc) loadChunk(c + 2);
    }

    // epilogue
    const int r_l = lane >> 2;
    const int c_l = (lane & 3) << 1;
    #pragma unroll
    for (int mb = 0; mb < 2; mb++) {
        #pragma unroll
        for (int nb = 0; nb < 8; nb++) {
            int row = m0 + wrow + mb * 16 + r_l;
            int col = n0 + wcol + nb * 8 + c_l;
            float b0 = bias[col], b1 = bias[col + 1];
            float v0 = acc[mb][nb][0] + b0;
            float v1 = acc[mb][nb][1] + b1;
            float v2 = acc[mb][nb][2] + b0;
            float v3 = acc[mb][nb][3] + b1;
            if (EPI == 1) {
                v0 = 0.5f * v0 * (1.f + erff(v0 * 0.70710678118654752f));
                v1 = 0.5f * v1 * (1.f + erff(v1 * 0.70710678118654752f));
                v2 = 0.5f * v2 * (1.f + erff(v2 * 0.70710678118654752f));
                v3 = 0.5f * v3 * (1.f + erff(v3 * 0.70710678118654752f));
            }
            *reinterpret_cast<float2*>(C + (size_t)row * N + col)       = make_float2(v0, v1);
            *reinterpret_cast<float2*>(C + (size_t)(row + 8) * N + col) = make_float2(v2, v3);
        }
    }
}

// ============================ attention (scalar FFMA, 4 key-slices) ============================
// scores(i,j) = (q_i*scale).k_j - pep[j,h]  (row-constant term cancels in softmax; fixed m=0 safe)
__global__ void __launch_bounds__(64) attn_part_kernel(const float* __restrict__ qkv,
                                                       const float* __restrict__ pep,
                                                       float* __restrict__ part,
                                                       float* __restrict__ plsum) {
    const int h  = blockIdx.y;
    const int sl = blockIdx.z;
    const int t  = threadIdx.x;
    const int i  = blockIdx.x * 64 + t;
    __shared__ float Ks[64][64];
    __shared__ float Vs[64][64];
    __shared__ float bs[64];

    const float* qp = qkv + (size_t)i * 1536 + h * 64;
    float q[64], acc[64];
    #pragma unroll
    for (int d = 0; d < 64; d++) { q[d] = qp[d] * 0.125f; acc[d] = 0.f; }
    float lsum = 0.f;

    for (int j0 = sl * 64; j0 < NN; j0 += 256) {
        __syncthreads();
        for (int x = t; x < 64 * 64; x += 64) {
            int j = x >> 6, d = x & 63;
            Ks[j][d] = qkv[(size_t)(j0 + j) * 1536 + 512  + h * 64 + d];
            Vs[j][d] = qkv[(size_t)(j0 + j) * 1536 + 1024 + h * 64 + d];
        }
        bs[t] = pep[(size_t)(j0 + t) * HH + h];
        __syncthreads();
        #pragma unroll 1
        for (int j = 0; j < 64; j++) {
            const float4* kr = reinterpret_cast<const float4*>(&Ks[j][0]);
            float s = -bs[j];
            #pragma unroll
            for (int d4 = 0; d4 < 16; d4++) {
                float4 kv = kr[d4];
                s += q[d4*4+0]*kv.x + q[d4*4+1]*kv.y + q[d4*4+2]*kv.z + q[d4*4+3]*kv.w;
            }
            float p = __expf(s);
            lsum += p;
            const float4* vr = reinterpret_cast<const float4*>(&Vs[j][0]);
            #pragma unroll
            for (int d4 = 0; d4 < 16; d4++) {
                float4 vv = vr[d4];
                acc[d4*4+0] += p * vv.x; acc[d4*4+1] += p * vv.y;
                acc[d4*4+2] += p * vv.z; acc[d4*4+3] += p * vv.w;
            }
        }
    }
    float* pp = part + ((size_t)(sl * HH + h) * NN + i) * 64;
    #pragma unroll
    for (int d = 0; d < 64; d++) pp[d] = acc[d];
    plsum[(size_t)(sl * HH + h) * NN + i] = lsum;
}

__global__ void attn_combine_kernel(const float* __restrict__ part, const float* __restrict__ pls,
                                    float* __restrict__ out) {
    int i = blockIdx.x, t = threadIdx.x;
    #pragma unroll
    for (int rep = 0; rep < 2; rep++) {
        int idx = t + rep * 256;
        int h = idx >> 6, d = idx & 63;
        float v = 0.f, l = 0.f;
        #pragma unroll
        for (int s = 0; s < 4; s++) {
            l += pls[(size_t)(s * HH + h) * NN + i];
            v += part[((size_t)(s * HH + h) * NN + i) * 64 + d];
        }
        out[(size_t)i * DD + idx] = v / l;
    }
}

// ============================ misc ============================
__global__ void copy_x_kernel(const float* __restrict__ src) {
    size_t idx = (size_t)blockIdx.x * blockDim.x + threadIdx.x;
    float4* dst = reinterpret_cast<float4*>(g_x);
    const float4* s4 = reinterpret_cast<const float4*>(src);
    if (idx * 4 < (size_t)NN * DD) dst[idx] = s4[idx];
}
__global__ void ln_kernel(const float* __restrict__ a, const float* __restrict__ b,
                          const float* __restrict__ g, const float* __restrict__ be,
                          float* __restrict__ out) {
    __shared__ float sh[256];
    __shared__ float s_mu, s_r;
    int i = blockIdx.x, t = threadIdx.x;
    float v0 = a[(size_t)i * DD + t]       + b[(size_t)i * DD + t];
    float v1 = a[(size_t)i * DD + 256 + t] + b[(size_t)i * DD + 256 + t];
    sh[t] = v0 + v1; __syncthreads();
    for (int k = 128; k > 0; k >>= 1) { if (t < k) sh[t] += sh[t + k]; __syncthreads(); }
    if (t == 0) s_mu = sh[0] * (1.f / DD);
    __syncthreads();
    float mu = s_mu;
    float d0 = v0 - mu, d1 = v1 - mu;
    sh[t] = d0 * d0 + d1 * d1; __syncthreads();
    for (int k = 128; k > 0; k >>= 1) { if (t < k) sh[t] += sh[t + k]; __syncthreads(); }
    if (t == 0) s_r = rsqrtf(sh[0] * (1.f / DD) + 1e-5f);
    __syncthreads();
    float r = s_r;
    out[(size_t)i * DD + t]       = d0 * r * g[t]       + be[t];
    out[(size_t)i * DD + 256 + t] = d1 * r * g[256 + t] + be[256 + t];
}

// ============================ launch ============================
extern "C" void kernel_launch(void* const* d_in, const int* in_sizes, int n_in,
                              void* d_out, int out_size) {
    const float* node_features = (const float*)d_in[0];
    const int*   edge_index    = (const int*)  d_in[1];
    const float* pe_proj_W     = (const float*)d_in[2];
    const float* pe_proj_b     = (const float*)d_in[3];
    const float* qkv_W         = (const float*)d_in[4];
    const float* qkv_b         = (const float*)d_in[5];
    const float* peb_W         = (const float*)d_in[6];
    const float* peb_b         = (const float*)d_in[7];
    const float* out_W         = (const float*)d_in[8];
    const float* out_b         = (const float*)d_in[9];
    const float* ffn_W1        = (const float*)d_in[10];
    const float* ffn_b1        = (const float*)d_in[11];
    const float* ffn_W2        = (const float*)d_in[12];
    const float* ffn_b2        = (const float*)d_in[13];
    const float* ln1_g         = (const float*)d_in[14];
    const float* ln1_b         = (const float*)d_in[15];
    const float* ln2_g         = (const float*)d_in[16];
    const float* ln2_b         = (const float*)d_in[17];
    float* outp = (float*)d_out;

    float *T_, *T2_, *T3_, *T4_, *x_, *x1_, *qkv_, *attn_, *o_, *h_, *pep_, *part_, *pls_;
    __nv_bfloat16 *Ahi_, *Alo_, *qWh_, *qWl_, *oWh_, *oWl_, *f1h_, *f1l_, *f2h_, *f2l_;
    cudaGetSymbolAddress((void**)&T_,   g_T);
    cudaGetSymbolAddress((void**)&T2_,  g_T2);
    cudaGetSymbolAddress((void**)&T3_,  g_T3);
    cudaGetSymbolAddress((void**)&T4_,  g_T4);
    cudaGetSymbolAddress((void**)&x_,   g_x);
    cudaGetSymbolAddress((void**)&x1_,  g_x1);
    cudaGetSymbolAddress((void**)&qkv_, g_qkv);
    cudaGetSymbolAddress((void**)&attn_,g_attn);
    cudaGetSymbolAddress((void**)&o_,   g_o);
    cudaGetSymbolAddress((void**)&h_,   g_h);
    cudaGetSymbolAddress((void**)&pep_, g_pep);
    cudaGetSymbolAddress((void**)&part_,g_part);
    cudaGetSymbolAddress((void**)&pls_, g_plsum);
    cudaGetSymbolAddress((void**)&Ahi_, g_Ahi);
    cudaGetSymbolAddress((void**)&Alo_, g_Alo);
    cudaGetSymbolAddress((void**)&qWh_, g_qkvW_hi);
    cudaGetSymbolAddress((void**)&qWl_, g_qkvW_lo);
    cudaGetSymbolAddress((void**)&oWh_, g_outW_hi);
    cudaGetSymbolAddress((void**)&oWl_, g_outW_lo);
    cudaGetSymbolAddress((void**)&f1h_, g_f1W_hi);
    cudaGetSymbolAddress((void**)&f1l_, g_f1W_lo);
    cudaGetSymbolAddress((void**)&f2h_, g_f2W_hi);
    cudaGetSymbolAddress((void**)&f2l_, g_f2W_lo);

    cudaFuncSetAttribute(mma_gemm_kernel<0>, cudaFuncAttributeMaxDynamicSharedMemorySize, GSMEM_TOTAL);
    cudaFuncSetAttribute(mma_gemm_kernel<1>, cudaFuncAttributeMaxDynamicSharedMemorySize, GSMEM_TOTAL);

    // ---- weight conversion (transpose + bf16 hi/lo split) ----
    for (int l = 0; l < LLC; l++) {
        convW_kernel<<<dim3(1536/32, 512/32),  dim3(32,8)>>>(qkv_W  + (size_t)l*DD*3*DD,  qWh_ + (size_t)l*3*DD*DD,  qWl_ + (size_t)l*3*DD*DD,  DD,  3*DD);
        convW_kernel<<<dim3(512/32,  512/32),  dim3(32,8)>>>(out_W  + (size_t)l*DD*DD,    oWh_ + (size_t)l*DD*DD,    oWl_ + (size_t)l*DD*DD,    DD,  DD);
        convW_kernel<<<dim3(2048/32, 512/32),  dim3(32,8)>>>(ffn_W1 + (size_t)l*DD*DFFC,  f1h_ + (size_t)l*DD*DFFC,  f1l_ + (size_t)l*DD*DFFC,  DD,  DFFC);
        convW_kernel<<<dim3(512/32,  2048/32), dim3(32,8)>>>(ffn_W2 + (size_t)l*DFFC*DD,  f2h_ + (size_t)l*DFFC*DD,  f2l_ + (size_t)l*DFFC*DD,  DFFC, DD);
    }

    // ---- PE pipeline ----
    zero_T_kernel<<<4096, 256>>>();
    scatter_kernel<<<EEC / 256, 256>>>(edge_index);
    deg_kernel<<<NN, 256>>>();
    buildT_kernel<<<NN, 256>>>();
    spmm_kernel<<<NN, 256>>>(T_,  T2_);
    spmm_kernel<<<NN, 256>>>(T2_, T3_);
    spmm_kernel<<<NN, 256>>>(T3_, T4_);
    diag_kernel<<<NN, 256>>>();
    pe_kernel<<<(NN + 127) / 128, 128>>>(pe_proj_W, pe_proj_b);
    pep_kernel<<<(NN + 127) / 128, 128>>>(peb_W, peb_b);

    // ---- transformer ----
    copy_x_kernel<<<1024, 256>>>(node_features);
    for (int l = 0; l < LLC; l++) {
        // qkv = x @ qkv_W + b
        splitA_kernel<<<2048, 256>>>(x_, Ahi_, Alo_, NN * DD);
        mma_gemm_kernel<0><<<dim3(1536/128, NN/128), 256, GSMEM_TOTAL>>>(
            Ahi_, Alo_, qWh_ + (size_t)l*3*DD*DD, qWl_ + (size_t)l*3*DD*DD,
            qkv_b + (size_t)l*3*DD, qkv_, 3*DD, DD);
        // attention
        attn_part_kernel<<<dim3(NN/64, HH, 4), 64>>>(qkv_, pep_ + (size_t)l*NN*HH, part_, pls_);
        attn_combine_kernel<<<NN, 256>>>(part_, pls_, attn_);
        // o = attn @ out_W + b
        splitA_kernel<<<2048, 256>>>(attn_, Ahi_, Alo_, NN * DD);
        mma_gemm_kernel<0><<<dim3(DD/128, NN/128), 256, GSMEM_TOTAL>>>(
            Ahi_, Alo_, oWh_ + (size_t)l*DD*DD, oWl_ + (size_t)l*DD*DD,
            out_b + (size_t)l*DD, o_, DD, DD);
        ln_kernel<<<NN, 256>>>(x_, o_, ln1_g + (size_t)l*DD, ln1_b + (size_t)l*DD, x1_);
        // h = gelu(x1 @ ffn_W1 + b)
        splitA_kernel<<<2048, 256>>>(x1_, Ahi_, Alo_, NN * DD);
        mma_gemm_kernel<1><<<dim3(DFFC/128, NN/128), 256, GSMEM_TOTAL>>>(
            Ahi_, Alo_, f1h_ + (size_t)l*DD*DFFC, f1l_ + (size_t)l*DD*DFFC,
            ffn_b1 + (size_t)l*DFFC, h_, DFFC, DD);
        // o = h @ ffn_W2 + b
        splitA_kernel<<<4096, 256>>>(h_, Ahi_, Alo_, NN * DFFC);
        mma_gemm_kernel<0><<<dim3(DD/128, NN/128), 256, GSMEM_TOTAL>>>(
            Ahi_, Alo_, f2h_ + (size_t)l*DFFC*DD, f2l_ + (size_t)l*DFFC*DD,
            ffn_b2 + (size_t)l*DD, o_, DD, DFFC);
        float* xout = (l == LLC - 1) ? outp : x_;
        ln_kernel<<<NN, 256>>>(x1_, o_, ln2_g + (size_t)l*DD, ln2_b + (size_t)l*DD, xout);
    }
}

// round 4
// speedup vs baseline: 4.0661x; 2.0989x over previous
#include <cuda_runtime.h>
#include <cuda_bf16.h>
#include <math.h>
#include <stdint.h>

#define NN   2048
#define DD   512
#define HH   8
#define DPEC 16
#define WALKC 8
#define LLC  3
#define EEC  32768
#define DFFC 2048
#define MAXD 256

// ============================ PTX helpers (sm_80-baseline ISA only) ============================
__device__ __forceinline__ uint32_t smem_to_u32(const void* p) {
    uint32_t a;
    asm("{ .reg .u64 t; cvta.to.shared.u64 t, %1; cvt.u32.u64 %0, t; }" : "=r"(a) : "l"(p));
    return a;
}
#define CP_ASYNC16(dst, src) \
    asm volatile("cp.async.cg.shared.global [%0], [%1], 16;" :: "r"(dst), "l"(src))
#define CP_COMMIT() asm volatile("cp.async.commit_group;" ::: "memory")
#define CP_WAIT1()  asm volatile("cp.async.wait_group 1;" ::: "memory")
#define CP_WAIT0()  asm volatile("cp.async.wait_group 0;" ::: "memory")

__device__ __forceinline__ void ldsm4(uint32_t* r, uint32_t addr) {
    asm volatile("ldmatrix.sync.aligned.m8n8.x4.shared.b16 {%0,%1,%2,%3}, [%4];"
        : "=r"(r[0]), "=r"(r[1]), "=r"(r[2]), "=r"(r[3]) : "r"(addr));
}
__device__ __forceinline__ void ldsm4t(uint32_t* r, uint32_t addr) {
    asm volatile("ldmatrix.sync.aligned.m8n8.x4.trans.shared.b16 {%0,%1,%2,%3}, [%4];"
        : "=r"(r[0]), "=r"(r[1]), "=r"(r[2]), "=r"(r[3]) : "r"(addr));
}
__device__ __forceinline__ void mma16816(float* c, const uint32_t* a, const uint32_t* b) {
    asm volatile("mma.sync.aligned.m16n8k16.row.col.f32.bf16.bf16.f32 "
        "{%0,%1,%2,%3}, {%4,%5,%6,%7}, {%8,%9}, {%0,%1,%2,%3};"
        : "+f"(c[0]), "+f"(c[1]), "+f"(c[2]), "+f"(c[3])
        : "r"(a[0]), "r"(a[1]), "r"(a[2]), "r"(a[3]), "r"(b[0]), "r"(b[1]));
}

#define ASM_OFF(row, ch) ((uint32_t)((row) * 128 + ((((ch)) ^ ((row) & 7)) << 4)))

// ============================ static device scratch ============================
__device__ float g_T [NN*NN];
__device__ float g_T2[NN*NN];
__device__ float g_T3[NN*NN];
__device__ float g_T4[NN*NN];
__device__ float g_deg[NN];
__device__ float g_invdeg[NN];
__device__ int   g_nbr[NN*MAXD];
__device__ int   g_cnt[NN];
__device__ float g_rw [NN*WALKC];
__device__ float g_pe [NN*DPEC];
__device__ float g_pep[LLC*NN*HH];
__device__ float g_x   [NN*DD];
__device__ float g_x1  [NN*DD];
__device__ float g_o   [NN*DD];
__device__ __nv_bfloat16 g_Ahi[NN*DD];
__device__ __nv_bfloat16 g_Alo[NN*DD];
__device__ __nv_bfloat16 g_Hhi[NN*DFFC];
__device__ __nv_bfloat16 g_Hlo[NN*DFFC];
__device__ __nv_bfloat16 g_QKVhi[NN*3*DD];
__device__ __nv_bfloat16 g_QKVlo[NN*3*DD];
__device__ __nv_bfloat16 g_qkvW_hi[LLC*3*DD*DD];
__device__ __nv_bfloat16 g_qkvW_lo[LLC*3*DD*DD];
__device__ __nv_bfloat16 g_outW_hi[LLC*DD*DD];
__device__ __nv_bfloat16 g_outW_lo[LLC*DD*DD];
__device__ __nv_bfloat16 g_f1W_hi[LLC*DD*DFFC];
__device__ __nv_bfloat16 g_f1W_lo[LLC*DD*DFFC];
__device__ __nv_bfloat16 g_f2W_hi[LLC*DFFC*DD];
__device__ __nv_bfloat16 g_f2W_lo[LLC*DFFC*DD];
__device__ float g_part [4*HH*NN*64];
__device__ float g_plsum[4*HH*NN];

// ============================ PE pipeline ============================
__global__ void zero_T_kernel() {
    size_t idx = (size_t)blockIdx.x * blockDim.x + threadIdx.x;
    float4* p = reinterpret_cast<float4*>(g_T);
    if (idx * 4 < (size_t)NN * NN) p[idx] = make_float4(0.f, 0.f, 0.f, 0.f);
}
__global__ void scatter_kernel(const int* __restrict__ ei) {
    int e = blockIdx.x * blockDim.x + threadIdx.x;
    if (e < EEC) {
        int s = ei[e], t = ei[EEC + e];
        g_T[(size_t)s * NN + t] = 1.f;
        g_T[(size_t)t * NN + s] = 1.f;
    }
}
__global__ void deg_kernel() {
    __shared__ float sh[256];
    int i = blockIdx.x, t = threadIdx.x;
    float s = 0.f;
    const float* row = g_T + (size_t)i * NN;
    for (int j = t; j < NN; j += 256) s += row[j];
    sh[t] = s; __syncthreads();
    for (int k = 128; k > 0; k >>= 1) { if (t < k) sh[t] += sh[t + k]; __syncthreads(); }
    if (t == 0) {
        float d = sh[0] < 1.f ? 1.f : sh[0];
        g_deg[i] = d; g_invdeg[i] = 1.f / d;
    }
}
__global__ void buildT_kernel() {
    __shared__ int cnt;
    int i = blockIdx.x, t = threadIdx.x;
    if (t == 0) cnt = 0;
    __syncthreads();
    float inv = g_invdeg[i];
    float* row = g_T + (size_t)i * NN;
    for (int j = t; j < NN; j += 256) {
        float a = row[j];
        if (a != 0.f) {
            int p = atomicAdd(&cnt, 1);
            if (p < MAXD) g_nbr[i * MAXD + p] = j;
            row[j] = a * inv;
        }
    }
    __syncthreads();
    if (t == 0) g_cnt[i] = cnt < MAXD ? cnt : MAXD;
}
__global__ void __launch_bounds__(256) spmm_kernel(const float* __restrict__ IN, float* __restrict__ OUT) {
    int i = blockIdx.x, t = threadIdx.x;
    int cnt = g_cnt[i];
    float inv = g_invdeg[i];
    const int* nb = g_nbr + i * MAXD;
    float acc[8] = {};
    for (int c = 0; c < cnt; c++) {
        const float* row = IN + (size_t)nb[c] * NN;
        #pragma unroll
        for (int u = 0; u < 8; u++) acc[u] += row[t + u * 256];
    }
    float* out = OUT + (size_t)i * NN;
    #pragma unroll
    for (int u = 0; u < 8; u++) out[t + u * 256] = acc[u] * inv;
}
__global__ void diag_kernel() {
    __shared__ float sh[256];
    __shared__ float res[7];
    int i = blockIdx.x, t = threadIdx.x;
    const float* r1 = g_T  + (size_t)i * NN;
    const float* r2 = g_T2 + (size_t)i * NN;
    const float* r3 = g_T3 + (size_t)i * NN;
    const float* r4 = g_T4 + (size_t)i * NN;
    float s[7] = {};
    for (int j = t; j < NN; j += 256) {
        float w = g_invdeg[j];
        float a = r1[j], b = r2[j], c = r3[j], d = r4[j];
        s[0] += a * a * w; s[1] += b * a * w; s[2] += b * b * w;
        s[3] += c * b * w; s[4] += c * c * w; s[5] += d * c * w; s[6] += d * d * w;
    }
    for (int v = 0; v < 7; v++) {
        sh[t] = s[v]; __syncthreads();
        for (int k = 128; k > 0; k >>= 1) { if (t < k) sh[t] += sh[t + k]; __syncthreads(); }
        if (t == 0) res[v] = sh[0];
        __syncthreads();
    }
    if (t == 0) {
        float di = g_deg[i];
        g_rw[i * WALKC + 0] = r1[i];
        #pragma unroll
        for (int v = 0; v < 7; v++) g_rw[i * WALKC + 1 + v] = res[v] * di;
    }
}
__global__ void pe_kernel(const float* __restrict__ W, const float* __restrict__ b) {
    int i = blockIdx.x * blockDim.x + threadIdx.x;
    if (i >= NN) return;
    float r[WALKC];
    #pragma unroll
    for (int w = 0; w < WALKC; w++) r[w] = g_rw[i * WALKC + w];
    #pragma unroll
    for (int d = 0; d < DPEC; d++) {
        float s = b[d];
        #pragma unroll
        for (int w = 0; w < WALKC; w++) s += r[w] * W[w * DPEC + d];
        g_pe[i * DPEC + d] = s;
    }
}
__global__ void pep_kernel(const float* __restrict__ W, const float* __restrict__ b) {
    int i = blockIdx.x * blockDim.x + threadIdx.x;
    if (i >= NN) return;
    float p[DPEC];
    #pragma unroll
    for (int d = 0; d < DPEC; d++) p[d] = g_pe[i * DPEC + d];
    for (int l = 0; l < LLC; l++) {
        #pragma unroll
        for (int h = 0; h < HH; h++) {
            float s = b[l * HH + h];
            #pragma unroll
            for (int d = 0; d < DPEC; d++) s += p[d] * W[(l * DPEC + d) * HH + h];
            g_pep[(size_t)l * NN * HH + i * HH + h] = s;
        }
    }
}

// ============================ conversions ============================
__global__ void splitA_kernel(const float* __restrict__ a, __nv_bfloat16* __restrict__ hi,
                              __nv_bfloat16* __restrict__ lo, int n) {
    int idx = blockIdx.x * blockDim.x + threadIdx.x;
    for (int i = idx; i < n; i += gridDim.x * blockDim.x) {
        float v = a[i];
        __nv_bfloat16 h = __float2bfloat16_rn(v);
        hi[i] = h;
        lo[i] = __float2bfloat16_rn(v - __bfloat162float(h));
    }
}
__global__ void convW_kernel(const float* __restrict__ W, __nv_bfloat16* __restrict__ hi,
                             __nv_bfloat16* __restrict__ lo, int K, int N) {
    __shared__ float tile[32][33];
    int n0 = blockIdx.x * 32, k0 = blockIdx.y * 32;
    int tx = threadIdx.x, ty = threadIdx.y;
    #pragma unroll
    for (int r = 0; r < 4; r++)
        tile[ty + r * 8][tx] = W[(size_t)(k0 + ty + r * 8) * N + n0 + tx];
    __syncthreads();
    #pragma unroll
    for (int r = 0; r < 4; r++) {
        int ni = ty + r * 8;
        float v = tile[tx][ni];
        __nv_bfloat16 h = __float2bfloat16_rn(v);
        size_t o = (size_t)(n0 + ni) * K + k0 + tx;
        hi[o] = h;
        lo[o] = __float2bfloat16_rn(v - __bfloat162float(h));
    }
}

// ============================ mma.sync bf16x3 GEMM ============================
#define GSTAGE 65536
#define GSMEM_TOTAL (2 * GSTAGE)

template<int EPI>  // 0 fp32 out; 2 bf16 hi/lo out; 3 GELU + bf16 hi/lo out
__global__ void __launch_bounds__(256) mma_gemm_kernel(
    const __nv_bfloat16* __restrict__ Ahi, const __nv_bfloat16* __restrict__ Alo,
    const __nv_bfloat16* __restrict__ Bhi, const __nv_bfloat16* __restrict__ Blo,
    const float* __restrict__ bias, float* __restrict__ C,
    __nv_bfloat16* __restrict__ Chi, __nv_bfloat16* __restrict__ Clo, int N, int K)
{
    extern __shared__ char smem[];
    const int tid  = threadIdx.x;
    const int lane = tid & 31;
    const int wid  = tid >> 5;
    const int m0 = blockIdx.y * 128, n0 = blockIdx.x * 128;
    const int wrow = (wid >> 1) * 32;
    const int wcol = (wid & 1) * 64;
    const uint32_t sbase = smem_to_u32(smem);

    float acc[2][8][4];
    #pragma unroll
    for (int a = 0; a < 2; a++)
        #pragma unroll
        for (int b = 0; b < 8; b++)
            #pragma unroll
            for (int c = 0; c < 4; c++) acc[a][b][c] = 0.f;

    const int nc = K >> 6;

    auto loadChunk = [&](int c) {
        uint32_t sb = sbase + (uint32_t)(c & 1) * GSTAGE;
        int k0 = c << 6;
        #pragma unroll
        for (int t4 = 0; t4 < 4; t4++) {
            const __nv_bfloat16* s = (t4 == 0) ? Ahi : (t4 == 1) ? Alo : (t4 == 2) ? Bhi : Blo;
            int r0 = (t4 < 2) ? m0 : n0;
            #pragma unroll
            for (int it = 0; it < 4; it++) {
                int idx = it * 256 + tid;
                int row = idx >> 3, ch = idx & 7;
                const void* src = s + (size_t)(r0 + row) * K + k0 + ch * 8;
                uint32_t dst = sb + t4 * 16384 + ASM_OFF(row, ch);
                CP_ASYNC16(dst, src);
            }
        }
        CP_COMMIT();
    };

    loadChunk(0);
    if (nc > 1) loadChunk(1);

    for (int c = 0; c < nc; c++) {
        if (c + 1 < nc) CP_WAIT1(); else CP_WAIT0();
        __syncthreads();
        uint32_t sb = sbase + (uint32_t)(c & 1) * GSTAGE;
        uint32_t sAh = sb, sAl = sb + 16384, sBh = sb + 32768, sBl = sb + 49152;
        #pragma unroll
        for (int ks = 0; ks < 4; ks++) {
            uint32_t ah[2][4], al[2][4], bh[4][4], bl[4][4];
            {
                int sub = lane >> 3;
                int row16 = (lane & 7) + ((sub & 1) << 3);
                int kc = ks * 2 + (sub >> 1);
                #pragma unroll
                for (int mb = 0; mb < 2; mb++) {
                    int row = wrow + mb * 16 + row16;
                    uint32_t off = ASM_OFF(row, kc);
                    ldsm4(ah[mb], sAh + off);
                    ldsm4(al[mb], sAl + off);
                }
            }
            {
                int sub = lane >> 3;
                int kc = ks * 2 + (sub & 1);
                int nr = ((sub >> 1) << 3) + (lane & 7);
                #pragma unroll
                for (int j = 0; j < 4; j++) {
                    int row = wcol + j * 16 + nr;
                    uint32_t off = ASM_OFF(row, kc);
                    ldsm4(bh[j], sBh + off);
                    ldsm4(bl[j], sBl + off);
                }
            }
            #pragma unroll
            for (int mb = 0; mb < 2; mb++)
                #pragma unroll
                for (int j = 0; j < 4; j++) {
                    mma16816(acc[mb][2*j],     ah[mb], &bh[j][0]);
                    mma16816(acc[mb][2*j],     ah[mb], &bl[j][0]);
                    mma16816(acc[mb][2*j],     al[mb], &bh[j][0]);
                    mma16816(acc[mb][2*j + 1], ah[mb], &bh[j][2]);
                    mma16816(acc[mb][2*j + 1], ah[mb], &bl[j][2]);
                    mma16816(acc[mb][2*j + 1], al[mb], &bh[j][2]);
                }
        }
        __syncthreads();
        if (c + 2 < nc) loadChunk(c + 2);
    }

    const int r_l = lane >> 2;
    const int c_l = (lane & 3) << 1;
    #pragma unroll
    for (int mb = 0; mb < 2; mb++) {
        #pragma unroll
        for (int nb = 0; nb < 8; nb++) {
            int row = m0 + wrow + mb * 16 + r_l;
            int col = n0 + wcol + nb * 8 + c_l;
            float b0 = bias[col], b1 = bias[col + 1];
            float v0 = acc[mb][nb][0] + b0;
            float v1 = acc[mb][nb][1] + b1;
            float v2 = acc[mb][nb][2] + b0;
            float v3 = acc[mb][nb][3] + b1;
            if (EPI == 3) {
                v0 = 0.5f * v0 * (1.f + erff(v0 * 0.70710678118654752f));
                v1 = 0.5f * v1 * (1.f + erff(v1 * 0.70710678118654752f));
                v2 = 0.5f * v2 * (1.f + erff(v2 * 0.70710678118654752f));
                v3 = 0.5f * v3 * (1.f + erff(v3 * 0.70710678118654752f));
            }
            if (EPI == 0) {
                *reinterpret_cast<float2*>(C + (size_t)row * N + col)       = make_float2(v0, v1);
                *reinterpret_cast<float2*>(C + (size_t)(row + 8) * N + col) = make_float2(v2, v3);
            } else {
                __nv_bfloat162 h01 = __floats2bfloat162_rn(v0, v1);
                __nv_bfloat162 h23 = __floats2bfloat162_rn(v2, v3);
                __nv_bfloat162 l01 = __floats2bfloat162_rn(v0 - __bfloat162float(h01.x),
                                                           v1 - __bfloat162float(h01.y));
                __nv_bfloat162 l23 = __floats2bfloat162_rn(v2 - __bfloat162float(h23.x),
                                                           v3 - __bfloat162float(h23.y));
                *reinterpret_cast<__nv_bfloat162*>(Chi + (size_t)row * N + col)       = h01;
                *reinterpret_cast<__nv_bfloat162*>(Chi + (size_t)(row + 8) * N + col) = h23;
                *reinterpret_cast<__nv_bfloat162*>(Clo + (size_t)row * N + col)       = l01;
                *reinterpret_cast<__nv_bfloat162*>(Clo + (size_t)(row + 8) * N + col) = l23;
            }
        }
    }
}

// ============================ tensor-core attention ============================
#define AT_QH 0
#define AT_QL 16384
#define AT_KH 32768
#define AT_KL 40960
#define AT_VH 49152
#define AT_VL 57344
#define AT_BS 65536
#define AT_SMEM (65536 + 256)

__global__ void __launch_bounds__(128) attn_tc_kernel(
    const __nv_bfloat16* __restrict__ qh, const __nv_bfloat16* __restrict__ ql,
    const float* __restrict__ pep, float* __restrict__ part, float* __restrict__ plsum)
{
    extern __shared__ char sm[];
    const int h = blockIdx.y, sl = blockIdx.z;
    const int q0 = blockIdx.x * 128;
    const int tid = threadIdx.x, lane = tid & 31, wid = tid >> 5;
    const int wrow = wid * 32;
    const int sub = lane >> 3;
    const uint32_t sb = smem_to_u32(sm);
    float* bias = reinterpret_cast<float*>(sm + AT_BS);

    #pragma unroll
    for (int it = 0; it < 8; it++) {
        int idx = it * 128 + tid;
        int row = idx >> 3, ch = idx & 7;
        size_t g = (size_t)(q0 + row) * 1536 + h * 64 + ch * 8;
        uint32_t off = ASM_OFF(row, ch);
        CP_ASYNC16(sb + AT_QH + off, qh + g);
        CP_ASYNC16(sb + AT_QL + off, ql + g);
    }
    CP_COMMIT();

    float O[2][8][4];
    float ls[2][2] = {{0.f, 0.f}, {0.f, 0.f}};
    #pragma unroll
    for (int mb = 0; mb < 2; mb++)
        #pragma unroll
        for (int nb = 0; nb < 8; nb++)
            #pragma unroll
            for (int u = 0; u < 4; u++) O[mb][nb][u] = 0.f;

    for (int c = 0; c < 8; c++) {
        const int kk = sl * 512 + c * 64;
        #pragma unroll
        for (int it = 0; it < 4; it++) {
            int idx = it * 128 + tid;
            int row = idx >> 3, ch = idx & 7;
            size_t gk = (size_t)(kk + row) * 1536 + 512 + h * 64 + ch * 8;
            uint32_t off = ASM_OFF(row, ch);
            CP_ASYNC16(sb + AT_KH + off, qh + gk);
            CP_ASYNC16(sb + AT_KL + off, ql + gk);
            CP_ASYNC16(sb + AT_VH + off, qh + gk + 512);
            CP_ASYNC16(sb + AT_VL + off, ql + gk + 512);
        }
        if (tid < 64) bias[tid] = pep[(size_t)(kk + tid) * HH + h];
        CP_COMMIT();
        CP_WAIT0();
        __syncthreads();

        float S[2][8][4];
        #pragma unroll
        for (int mb = 0; mb < 2; mb++)
            #pragma unroll
            for (int nb = 0; nb < 8; nb++)
                #pragma unroll
                for (int u = 0; u < 4; u++) S[mb][nb][u] = 0.f;
        #pragma unroll
        for (int kb = 0; kb < 4; kb++) {
            uint32_t ah[2][4], al[2][4];
            int r16 = (lane & 7) + ((sub & 1) << 3);
            int chA = kb * 2 + (sub >> 1);
            #pragma unroll
            for (int mb = 0; mb < 2; mb++) {
                int row = wrow + mb * 16 + r16;
                uint32_t off = ASM_OFF(row, chA);
                ldsm4(ah[mb], sb + AT_QH + off);
                ldsm4(al[mb], sb + AT_QL + off);
            }
            int chB = kb * 2 + (sub & 1);
            int nr = ((sub >> 1) << 3) + (lane & 7);
            #pragma unroll
            for (int j = 0; j < 4; j++) {
                uint32_t bh[4], bl[4];
                int row = j * 16 + nr;
                uint32_t off = ASM_OFF(row, chB);
                ldsm4(bh, sb + AT_KH + off);
                ldsm4(bl, sb + AT_KL + off);
                #pragma unroll
                for (int mb = 0; mb < 2; mb++) {
                    mma16816(S[mb][2*j],   ah[mb], &bh[0]);
                    mma16816(S[mb][2*j],   al[mb], &bh[0]);
                    mma16816(S[mb][2*j],   ah[mb], &bl[0]);
                    mma16816(S[mb][2*j+1], ah[mb], &bh[2]);
                    mma16816(S[mb][2*j+1], al[mb], &bh[2]);
                    mma16816(S[mb][2*j+1], ah[mb], &bl[2]);
                }
            }
        }

        uint32_t Ph[2][8][2], Pl[2][8][2];
        #pragma unroll
        for (int mb = 0; mb < 2; mb++)
            #pragma unroll
            for (int nb = 0; nb < 8; nb++) {
                int col = nb * 8 + ((lane & 3) << 1);
                float b0 = bias[col], b1 = bias[col + 1];
                float p0 = __expf(fmaf(S[mb][nb][0], 0.125f, -b0));
                float p1 = __expf(fmaf(S[mb][nb][1], 0.125f, -b1));
                float p2 = __expf(fmaf(S[mb][nb][2], 0.125f, -b0));
                float p3 = __expf(fmaf(S[mb][nb][3], 0.125f, -b1));
                ls[mb][0] += p0 + p1;
                ls[mb][1] += p2 + p3;
                __nv_bfloat162 h01 = __floats2bfloat162_rn(p0, p1);
                __nv_bfloat162 h23 = __floats2bfloat162_rn(p2, p3);
                __nv_bfloat162 l01 = __floats2bfloat162_rn(p0 - __bfloat162float(h01.x),
                                                           p1 - __bfloat162float(h01.y));
                __nv_bfloat162 l23 = __floats2bfloat162_rn(p2 - __bfloat162float(h23.x),
                                                           p3 - __bfloat162float(h23.y));
                Ph[mb][nb][0] = *reinterpret_cast<uint32_t*>(&h01);
                Ph[mb][nb][1] = *reinterpret_cast<uint32_t*>(&h23);
                Pl[mb][nb][0] = *reinterpret_cast<uint32_t*>(&l01);
                Pl[mb][nb][1] = *reinterpret_cast<uint32_t*>(&l23);
            }

        #pragma unroll
        for (int kb2 = 0; kb2 < 4; kb2++) {
            int krow = kb2 * 16 + ((sub & 1) << 3) + (lane & 7);
            #pragma unroll
            for (int dI = 0; dI < 4; dI++) {
                uint32_t vh[4], vl[4];
                int ch = dI * 2 + (sub >> 1);
                uint32_t off = ASM_OFF(krow, ch);
                ldsm4t(vh, sb + AT_VH + off);
                ldsm4t(vl, sb + AT_VL + off);
                #pragma unroll
                for (int mb = 0; mb < 2; mb++) {
                    uint32_t pa[4] = {Ph[mb][2*kb2][0], Ph[mb][2*kb2][1],
                                      Ph[mb][2*kb2+1][0], Ph[mb][2*kb2+1][1]};
                    uint32_t la[4] = {Pl[mb][2*kb2][0], Pl[mb][2*kb2][1],
                                      Pl[mb][2*kb2+1][0], Pl[mb][2*kb2+1][1]};
                    mma16816(O[mb][2*dI],   pa, &vh[0]);
                    mma16816(O[mb][2*dI],   la, &vh[0]);
                    mma16816(O[mb][2*dI],   pa, &vl[0]);
                    mma16816(O[mb][2*dI+1], pa, &vh[2]);
                    mma16816(O[mb][2*dI+1], la, &vh[2]);
                    mma16816(O[mb][2*dI+1], pa, &vl[2]);
                }
            }
        }
        __syncthreads();
    }

    #pragma unroll
    for (int mb = 0; mb < 2; mb++)
        #pragma unroll
        for (int r = 0; r < 2; r++) {
            float v = ls[mb][r];
            v += __shfl_xor_sync(0xffffffffu, v, 1);
            v += __shfl_xor_sync(0xffffffffu, v, 2);
            ls[mb][r] = v;
        }
    const size_t base = (size_t)(sl * HH + h) * NN;
    #pragma unroll
    for (int mb = 0; mb < 2; mb++) {
        int rowA = q0 + wrow + mb * 16 + (lane >> 2);
        int rowB = rowA + 8;
        if ((lane & 3) == 0) {
            plsum[base + rowA] = ls[mb][0];
            plsum[base + rowB] = ls[mb][1];
        }
        #pragma unroll
        for (int nb = 0; nb < 8; nb++) {
            int col = nb * 8 + ((lane & 3) << 1);
            *reinterpret_cast<float2*>(part + (base + rowA) * 64 + col) = make_float2(O[mb][nb][0], O[mb][nb][1]);
            *reinterpret_cast<float2*>(part + (base + rowB) * 64 + col) = make_float2(O[mb][nb][2], O[mb][nb][3]);
        }
    }
}

__global__ void attn_combine_kernel(const float* __restrict__ part, const float* __restrict__ pls,
                                    __nv_bfloat16* __restrict__ ohi, __nv_bfloat16* __restrict__ olo) {
    int i = blockIdx.x, t = threadIdx.x;
    #pragma unroll
    for (int rep = 0; rep < 2; rep++) {
        int idx = t + rep * 256;
        int h = idx >> 6, d = idx & 63;
        float v = 0.f, l = 0.f;
        #pragma unroll
        for (int s = 0; s < 4; s++) {
            l += pls[(size_t)(s * HH + h) * NN + i];
            v += part[((size_t)(s * HH + h) * NN + i) * 64 + d];
        }
        float r = v / l;
        __nv_bfloat16 hb = __float2bfloat16_rn(r);
        ohi[(size_t)i * DD + idx] = hb;
        olo[(size_t)i * DD + idx] = __float2bfloat16_rn(r - __bfloat162float(hb));
    }
}

// ============================ misc ============================
__global__ void copy_x_kernel(const float* __restrict__ src) {
    size_t idx = (size_t)blockIdx.x * blockDim.x + threadIdx.x;
    float4* dst = reinterpret_cast<float4*>(g_x);
    const float4* s4 = reinterpret_cast<const float4*>(src);
    if (idx * 4 < (size_t)NN * DD) dst[idx] = s4[idx];
}
__global__ void ln_kernel(const float* __restrict__ a, const float* __restrict__ b,
                          const float* __restrict__ g, const float* __restrict__ be,
                          float* __restrict__ out,
                          __nv_bfloat16* __restrict__ ohi, __nv_bfloat16* __restrict__ olo) {
    __shared__ float sh[256];
    __shared__ float s_mu, s_r;
    int i = blockIdx.x, t = threadIdx.x;
    float v0 = a[(size_t)i * DD + t]       + b[(size_t)i * DD + t];
    float v1 = a[(size_t)i * DD + 256 + t] + b[(size_t)i * DD + 256 + t];
    sh[t] = v0 + v1; __syncthreads();
    for (int k = 128; k > 0; k >>= 1) { if (t < k) sh[t] += sh[t + k]; __syncthreads(); }
    if (t == 0) s_mu = sh[0] * (1.f / DD);
    __syncthreads();
    float mu = s_mu;
    float d0 = v0 - mu, d1 = v1 - mu;
    sh[t] = d0 * d0 + d1 * d1; __syncthreads();
    for (int k = 128; k > 0; k >>= 1) { if (t < k) sh[t] += sh[t + k]; __syncthreads(); }
    if (t == 0) s_r = rsqrtf(sh[0] * (1.f / DD) + 1e-5f);
    __syncthreads();
    float r = s_r;
    float o0 = d0 * r * g[t]       + be[t];
    float o1 = d1 * r * g[256 + t] + be[256 + t];
    out[(size_t)i * DD + t]       = o0;
    out[(size_t)i * DD + 256 + t] = o1;
    __nv_bfloat16 h0 = __float2bfloat16_rn(o0);
    __nv_bfloat16 h1 = __float2bfloat16_rn(o1);
    ohi[(size_t)i * DD + t]       = h0;
    ohi[(size_t)i * DD + 256 + t] = h1;
    olo[(size_t)i * DD + t]       = __float2bfloat16_rn(o0 - __bfloat162float(h0));
    olo[(size_t)i * DD + 256 + t] = __float2bfloat16_rn(o1 - __bfloat162float(h1));
}

// ============================ launch ============================
extern "C" void kernel_launch(void* const* d_in, const int* in_sizes, int n_in,
                              void* d_out, int out_size) {
    const float* node_features = (const float*)d_in[0];
    const int*   edge_index    = (const int*)  d_in[1];
    const float* pe_proj_W     = (const float*)d_in[2];
    const float* pe_proj_b     = (const float*)d_in[3];
    const float* qkv_W         = (const float*)d_in[4];
    const float* qkv_b         = (const float*)d_in[5];
    const float* peb_W         = (const float*)d_in[6];
    const float* peb_b         = (const float*)d_in[7];
    const float* out_W         = (const float*)d_in[8];
    const float* out_b         = (const float*)d_in[9];
    const float* ffn_W1        = (const float*)d_in[10];
    const float* ffn_b1        = (const float*)d_in[11];
    const float* ffn_W2        = (const float*)d_in[12];
    const float* ffn_b2        = (const float*)d_in[13];
    const float* ln1_g         = (const float*)d_in[14];
    const float* ln1_b         = (const float*)d_in[15];
    const float* ln2_g         = (const float*)d_in[16];
    const float* ln2_b         = (const float*)d_in[17];
    float* outp = (float*)d_out;

    float *T_, *T2_, *T3_, *T4_, *x_, *x1_, *o_, *pep_, *part_, *pls_;
    __nv_bfloat16 *Ahi_, *Alo_, *Hhi_, *Hlo_, *Qh_, *Ql_;
    __nv_bfloat16 *qWh_, *qWl_, *oWh_, *oWl_, *f1h_, *f1l_, *f2h_, *f2l_;
    cudaGetSymbolAddress((void**)&T_,   g_T);
    cudaGetSymbolAddress((void**)&T2_,  g_T2);
    cudaGetSymbolAddress((void**)&T3_,  g_T3);
    cudaGetSymbolAddress((void**)&T4_,  g_T4);
    cudaGetSymbolAddress((void**)&x_,   g_x);
    cudaGetSymbolAddress((void**)&x1_,  g_x1);
    cudaGetSymbolAddress((void**)&o_,   g_o);
    cudaGetSymbolAddress((void**)&pep_, g_pep);
    cudaGetSymbolAddress((void**)&part_,g_part);
    cudaGetSymbolAddress((void**)&pls_, g_plsum);
    cudaGetSymbolAddress((void**)&Ahi_, g_Ahi);
    cudaGetSymbolAddress((void**)&Alo_, g_Alo);
    cudaGetSymbolAddress((void**)&Hhi_, g_Hhi);
    cudaGetSymbolAddress((void**)&Hlo_, g_Hlo);
    cudaGetSymbolAddress((void**)&Qh_,  g_QKVhi);
    cudaGetSymbolAddress((void**)&Ql_,  g_QKVlo);
    cudaGetSymbolAddress((void**)&qWh_, g_qkvW_hi);
    cudaGetSymbolAddress((void**)&qWl_, g_qkvW_lo);
    cudaGetSymbolAddress((void**)&oWh_, g_outW_hi);
    cudaGetSymbolAddress((void**)&oWl_, g_outW_lo);
    cudaGetSymbolAddress((void**)&f1h_, g_f1W_hi);
    cudaGetSymbolAddress((void**)&f1l_, g_f1W_lo);
    cudaGetSymbolAddress((void**)&f2h_, g_f2W_hi);
    cudaGetSymbolAddress((void**)&f2l_, g_f2W_lo);

    cudaFuncSetAttribute(mma_gemm_kernel<0>, cudaFuncAttributeMaxDynamicSharedMemorySize, GSMEM_TOTAL);
    cudaFuncSetAttribute(mma_gemm_kernel<2>, cudaFuncAttributeMaxDynamicSharedMemorySize, GSMEM_TOTAL);
    cudaFuncSetAttribute(mma_gemm_kernel<3>, cudaFuncAttributeMaxDynamicSharedMemorySize, GSMEM_TOTAL);
    cudaFuncSetAttribute(attn_tc_kernel, cudaFuncAttributeMaxDynamicSharedMemorySize, AT_SMEM);

    for (int l = 0; l < LLC; l++) {
        convW_kernel<<<dim3(1536/32, 512/32),  dim3(32,8)>>>(qkv_W  + (size_t)l*DD*3*DD,  qWh_ + (size_t)l*3*DD*DD,  qWl_ + (size_t)l*3*DD*DD,  DD,  3*DD);
        convW_kernel<<<dim3(512/32,  512/32),  dim3(32,8)>>>(out_W  + (size_t)l*DD*DD,    oWh_ + (size_t)l*DD*DD,    oWl_ + (size_t)l*DD*DD,    DD,  DD);
        convW_kernel<<<dim3(2048/32, 512/32),  dim3(32,8)>>>(ffn_W1 + (size_t)l*DD*DFFC,  f1h_ + (size_t)l*DD*DFFC,  f1l_ + (size_t)l*DD*DFFC,  DD,  DFFC);
        convW_kernel<<<dim3(512/32,  2048/32), dim3(32,8)>>>(ffn_W2 + (size_t)l*DFFC*DD,  f2h_ + (size_t)l*DFFC*DD,  f2l_ + (size_t)l*DFFC*DD,  DFFC, DD);
    }

    zero_T_kernel<<<4096, 256>>>();
    scatter_kernel<<<EEC / 256, 256>>>(edge_index);
    deg_kernel<<<NN, 256>>>();
    buildT_kernel<<<NN, 256>>>();
    spmm_kernel<<<NN, 256>>>(T_,  T2_);
    spmm_kernel<<<NN, 256>>>(T2_, T3_);
    spmm_kernel<<<NN, 256>>>(T3_, T4_);
    diag_kernel<<<NN, 256>>>();
    pe_kernel<<<(NN + 127) / 128, 128>>>(pe_proj_W, pe_proj_b);
    pep_kernel<<<(NN + 127) / 128, 128>>>(peb_W, peb_b);

    copy_x_kernel<<<1024, 256>>>(node_features);
    splitA_kernel<<<2048, 256>>>(x_, Ahi_, Alo_, NN * DD);
    for (int l = 0; l < LLC; l++) {
        mma_gemm_kernel<2><<<dim3(1536/128, NN/128), 256, GSMEM_TOTAL>>>(
            Ahi_, Alo_, qWh_ + (size_t)l*3*DD*DD, qWl_ + (size_t)l*3*DD*DD,
            qkv_b + (size_t)l*3*DD, nullptr, Qh_, Ql_, 3*DD, DD);
        attn_tc_kernel<<<dim3(NN/128, HH, 4), 128, AT_SMEM>>>(Qh_, Ql_, pep_ + (size_t)l*NN*HH, part_, pls_);
        attn_combine_kernel<<<NN, 256>>>(part_, pls_, Ahi_, Alo_);
        mma_gemm_kernel<0><<<dim3(DD/128, NN/128), 256, GSMEM_TOTAL>>>(
            Ahi_, Alo_, oWh_ + (size_t)l*DD*DD, oWl_ + (size_t)l*DD*DD,
            out_b + (size_t)l*DD, o_, nullptr, nullptr, DD, DD);
        ln_kernel<<<NN, 256>>>(x_, o_, ln1_g + (size_t)l*DD, ln1_b + (size_t)l*DD, x1_, Ahi_, Alo_);
        mma_gemm_kernel<3><<<dim3(DFFC/128, NN/128), 256, GSMEM_TOTAL>>>(
            Ahi_, Alo_, f1h_ + (size_t)l*DD*DFFC, f1l_ + (size_t)l*DD*DFFC,
            ffn_b1 + (size_t)l*DFFC, nullptr, Hhi_, Hlo_, DFFC, DD);
        mma_gemm_kernel<0><<<dim3(DD/128, NN/128), 256, GSMEM_TOTAL>>>(
            Hhi_, Hlo_, f2h_ + (size_t)l*DFFC*DD, f2l_ + (size_t)l*DFFC*DD,
            ffn_b2 + (size_t)l*DD, o_, nullptr, nullptr, DD, DFFC);
        float* xout = (l == LLC - 1) ? outp : x_;
        ln_kernel<<<NN, 256>>>(x1_, o_, ln2_g + (size_t)l*DD, ln2_b + (size_t)l*DD, xout, Ahi_, Alo_);
    }
}

// round 5
// speedup vs baseline: 4.8869x; 1.2019x over previous
#include <cuda_runtime.h>
#include <cuda_bf16.h>
#include <math.h>
#include <stdint.h>

#define NN   2048
#define DD   512
#define HH   8
#define DPEC 16
#define WALKC 8
#define LLC  3
#define EEC  32768
#define DFFC 2048
#define MAXD 256

// ============================ PTX helpers (sm_80-baseline ISA only) ============================
__device__ __forceinline__ uint32_t smem_to_u32(const void* p) {
    uint32_t a;
    asm("{ .reg .u64 t; cvta.to.shared.u64 t, %1; cvt.u32.u64 %0, t; }" : "=r"(a) : "l"(p));
    return a;
}
#define CP_ASYNC16(dst, src) \
    asm volatile("cp.async.cg.shared.global [%0], [%1], 16;" :: "r"(dst), "l"(src))
#define CP_COMMIT() asm volatile("cp.async.commit_group;" ::: "memory")
#define CP_WAIT1()  asm volatile("cp.async.wait_group 1;" ::: "memory")
#define CP_WAIT0()  asm volatile("cp.async.wait_group 0;" ::: "memory")

__device__ __forceinline__ void ldsm4(uint32_t* r, uint32_t addr) {
    asm volatile("ldmatrix.sync.aligned.m8n8.x4.shared.b16 {%0,%1,%2,%3}, [%4];"
        : "=r"(r[0]), "=r"(r[1]), "=r"(r[2]), "=r"(r[3]) : "r"(addr));
}
__device__ __forceinline__ void ldsm4t(uint32_t* r, uint32_t addr) {
    asm volatile("ldmatrix.sync.aligned.m8n8.x4.trans.shared.b16 {%0,%1,%2,%3}, [%4];"
        : "=r"(r[0]), "=r"(r[1]), "=r"(r[2]), "=r"(r[3]) : "r"(addr));
}
__device__ __forceinline__ void mma16816(float* c, const uint32_t* a, const uint32_t* b) {
    asm volatile("mma.sync.aligned.m16n8k16.row.col.f32.bf16.bf16.f32 "
        "{%0,%1,%2,%3}, {%4,%5,%6,%7}, {%8,%9}, {%0,%1,%2,%3};"
        : "+f"(c[0]), "+f"(c[1]), "+f"(c[2]), "+f"(c[3])
        : "r"(a[0]), "r"(a[1]), "r"(a[2]), "r"(a[3]), "r"(b[0]), "r"(b[1]));
}

#define ASM_OFF(row, ch) ((uint32_t)((row) * 128 + ((((ch)) ^ ((row) & 7)) << 4)))

// ============================ static device scratch ============================
__device__ uint32_t g_bm[NN*64];                // adjacency bitmap (2048 bits/row)
__device__ float g_deg[NN];
__device__ float g_invdeg[NN];
__device__ int   g_nbr[NN*MAXD];
__device__ int   g_cnt[NN];
__device__ __nv_bfloat16 g_T2b[NN*NN];
__device__ __nv_bfloat16 g_T3b[NN*NN];
__device__ __nv_bfloat16 g_T4b[NN*NN];
__device__ float g_rw [NN*WALKC];
__device__ float g_pe [NN*DPEC];
__device__ float g_pep[LLC*NN*HH];
__device__ float g_x   [NN*DD];
__device__ float g_x1  [NN*DD];
__device__ float g_o   [NN*DD];
__device__ __nv_bfloat16 g_Ahi[NN*DD];
__device__ __nv_bfloat16 g_Alo[NN*DD];
__device__ __nv_bfloat16 g_Hhi[NN*DFFC];
__device__ __nv_bfloat16 g_Hlo[NN*DFFC];
__device__ __nv_bfloat16 g_QKVhi[NN*3*DD];
__device__ __nv_bfloat16 g_QKVlo[NN*3*DD];
__device__ __nv_bfloat16 g_qkvW_hi[LLC*3*DD*DD];
__device__ __nv_bfloat16 g_qkvW_lo[LLC*3*DD*DD];
__device__ __nv_bfloat16 g_outW_hi[LLC*DD*DD];
__device__ __nv_bfloat16 g_outW_lo[LLC*DD*DD];
__device__ __nv_bfloat16 g_f1W_hi[LLC*DD*DFFC];
__device__ __nv_bfloat16 g_f1W_lo[LLC*DD*DFFC];
__device__ __nv_bfloat16 g_f2W_hi[LLC*DFFC*DD];
__device__ __nv_bfloat16 g_f2W_lo[LLC*DFFC*DD];
__device__ float g_part [4*HH*NN*64];
__device__ float g_plsum[4*HH*NN];

// ============================ PE pipeline (sparse) ============================
__global__ void zero_bm_kernel() {
    int idx = blockIdx.x * blockDim.x + threadIdx.x;
    if (idx < NN * 64) g_bm[idx] = 0u;
}
__global__ void scatter_bm_kernel(const int* __restrict__ ei) {
    int e = blockIdx.x * blockDim.x + threadIdx.x;
    if (e < EEC) {
        int s = ei[e], t = ei[EEC + e];
        atomicOr(&g_bm[s * 64 + (t >> 5)], 1u << (t & 31));
        atomicOr(&g_bm[t * 64 + (s >> 5)], 1u << (s & 31));
    }
}
// block(64) per row: bitmap -> neighbor list + degree
__global__ void build_bm_kernel() {
    __shared__ int cnt;
    int i = blockIdx.x, t = threadIdx.x;
    if (t == 0) cnt = 0;
    __syncthreads();
    uint32_t w = g_bm[i * 64 + t];
    int c = __popc(w);
    int pos = (c > 0) ? atomicAdd(&cnt, c) : 0;
    while (w) {
        int b = __ffs(w) - 1;
        w &= w - 1;
        if (pos < MAXD) g_nbr[i * MAXD + pos] = t * 32 + b;
        pos++;
    }
    __syncthreads();
    if (t == 0) {
        int cc = cnt < MAXD ? cnt : MAXD;
        g_cnt[i] = cc;
        float d = cnt < 1 ? 1.f : (float)cnt;
        g_deg[i] = d;
        g_invdeg[i] = 1.f / d;
    }
}
// T2 = T@T via sparse-sparse scatter into an smem row; output bf16
__global__ void __launch_bounds__(256) t2_kernel() {
    __shared__ float rowbuf[NN];
    int i = blockIdx.x, t = threadIdx.x;
    #pragma unroll
    for (int u = 0; u < NN / 256; u++) rowbuf[t + u * 256] = 0.f;
    __syncthreads();
    int cnt = g_cnt[i];
    float inv_i = g_invdeg[i];
    for (int c = t >> 3; c < cnt; c += 32) {
        int j = g_nbr[i * MAXD + c];
        float w = inv_i * g_invdeg[j];
        int cj = g_cnt[j];
        const int* nbj = g_nbr + j * MAXD;
        for (int k = t & 7; k < cj; k += 8) atomicAdd(&rowbuf[nbj[k]], w);
    }
    __syncthreads();
    __nv_bfloat16* out = g_T2b + (size_t)i * NN;
    #pragma unroll
    for (int u = 0; u < NN / 256; u++) {
        int idx = t + u * 256;
        out[idx] = __float2bfloat16_rn(rowbuf[idx]);
    }
}
// OUT = T @ IN  (IN dense bf16 rows, T sparse)
__global__ void __launch_bounds__(256) spmm_bf_kernel(const __nv_bfloat16* __restrict__ IN,
                                                      __nv_bfloat16* __restrict__ OUT) {
    int i = blockIdx.x, t = threadIdx.x;
    int cnt = g_cnt[i];
    float inv = g_invdeg[i];
    const int* nb = g_nbr + i * MAXD;
    float2 acc[4];
    #pragma unroll
    for (int u = 0; u < 4; u++) acc[u] = make_float2(0.f, 0.f);
    for (int c = 0; c < cnt; c++) {
        const __nv_bfloat162* row = reinterpret_cast<const __nv_bfloat162*>(IN + (size_t)nb[c] * NN);
        #pragma unroll
        for (int u = 0; u < 4; u++) {
            float2 v = __bfloat1622float2(row[t + u * 256]);
            acc[u].x += v.x; acc[u].y += v.y;
        }
    }
    __nv_bfloat162* out = reinterpret_cast<__nv_bfloat162*>(OUT + (size_t)i * NN);
    #pragma unroll
    for (int u = 0; u < 4; u++)
        out[t + u * 256] = __floats2bfloat162_rn(acc[u].x * inv, acc[u].y * inv);
}
// diagonals of T^1..T^8 from sparse T + dense bf16 T2/T3/T4
__global__ void diag2_kernel() {
    __shared__ float sh[256];
    __shared__ float res[7];
    int i = blockIdx.x, t = threadIdx.x;
    float inv_i = g_invdeg[i], d_i = g_deg[i];
    int cnt = g_cnt[i];
    const __nv_bfloat16* r2 = g_T2b + (size_t)i * NN;
    const __nv_bfloat16* r3 = g_T3b + (size_t)i * NN;
    const __nv_bfloat16* r4 = g_T4b + (size_t)i * NN;
    float s[7] = {};
    for (int c = t; c < cnt; c += 256) {
        int j = g_nbr[i * MAXD + c];
        float wj = g_invdeg[j];
        s[0] += wj;                                  // -> diag T2
        s[1] += __bfloat162float(r2[j]) * wj;        // -> diag T3
    }
    for (int j = t; j < NN; j += 256) {
        float w = g_invdeg[j];
        float t2 = __bfloat162float(r2[j]);
        float t3 = __bfloat162float(r3[j]);
        float t4 = __bfloat162float(r4[j]);
        s[2] += t2 * t2 * w;   // T4
        s[3] += t3 * t2 * w;   // T5
        s[4] += t3 * t3 * w;   // T6
        s[5] += t4 * t3 * w;   // T7
        s[6] += t4 * t4 * w;   // T8
    }
    for (int v = 0; v < 7; v++) {
        sh[t] = s[v]; __syncthreads();
        for (int k = 128; k > 0; k >>= 1) { if (t < k) sh[t] += sh[t + k]; __syncthreads(); }
        if (t == 0) res[v] = sh[0];
        __syncthreads();
    }
    if (t == 0) {
        bool self = (g_bm[i * 64 + (i >> 5)] >> (i & 31)) & 1u;
        g_rw[i * WALKC + 0] = self ? inv_i : 0.f;
        g_rw[i * WALKC + 1] = inv_i * res[0];
        g_rw[i * WALKC + 2] = res[1];
        g_rw[i * WALKC + 3] = d_i * res[2];
        g_rw[i * WALKC + 4] = d_i * res[3];
        g_rw[i * WALKC + 5] = d_i * res[4];
        g_rw[i * WALKC + 6] = d_i * res[5];
        g_rw[i * WALKC + 7] = d_i * res[6];
    }
}
__global__ void pe_kernel(const float* __restrict__ W, const float* __restrict__ b) {
    int i = blockIdx.x * blockDim.x + threadIdx.x;
    if (i >= NN) return;
    float r[WALKC];
    #pragma unroll
    for (int w = 0; w < WALKC; w++) r[w] = g_rw[i * WALKC + w];
    #pragma unroll
    for (int d = 0; d < DPEC; d++) {
        float s = b[d];
        #pragma unroll
        for (int w = 0; w < WALKC; w++) s += r[w] * W[w * DPEC + d];
        g_pe[i * DPEC + d] = s;
    }
}
__global__ void pep_kernel(const float* __restrict__ W, const float* __restrict__ b) {
    int i = blockIdx.x * blockDim.x + threadIdx.x;
    if (i >= NN) return;
    float p[DPEC];
    #pragma unroll
    for (int d = 0; d < DPEC; d++) p[d] = g_pe[i * DPEC + d];
    for (int l = 0; l < LLC; l++) {
        #pragma unroll
        for (int h = 0; h < HH; h++) {
            float s = b[l * HH + h];
            #pragma unroll
            for (int d = 0; d < DPEC; d++) s += p[d] * W[(l * DPEC + d) * HH + h];
            g_pep[(size_t)l * NN * HH + i * HH + h] = s;
        }
    }
}

// ============================ conversions ============================
// copy x (fp32) + bf16 hi/lo split in one pass
__global__ void split_copy_kernel(const float* __restrict__ src) {
    int idx = blockIdx.x * blockDim.x + threadIdx.x;
    if (idx < NN * DD) {
        float v = src[idx];
        g_x[idx] = v;
        __nv_bfloat16 h = __float2bfloat16_rn(v);
        g_Ahi[idx] = h;
        g_Alo[idx] = __float2bfloat16_rn(v - __bfloat162float(h));
    }
}
// Weight transpose+split, layer-batched over blockIdx.z
__global__ void convW_kernel(const float* __restrict__ W, __nv_bfloat16* __restrict__ hi,
                             __nv_bfloat16* __restrict__ lo, int K, int N) {
    __shared__ float tile[32][33];
    size_t lw = (size_t)blockIdx.z * K * N;
    int n0 = blockIdx.x * 32, k0 = blockIdx.y * 32;
    int tx = threadIdx.x, ty = threadIdx.y;
    #pragma unroll
    for (int r = 0; r < 4; r++)
        tile[ty + r * 8][tx] = W[lw + (size_t)(k0 + ty + r * 8) * N + n0 + tx];
    __syncthreads();
    #pragma unroll
    for (int r = 0; r < 4; r++) {
        int ni = ty + r * 8;
        float v = tile[tx][ni];
        __nv_bfloat16 h = __float2bfloat16_rn(v);
        size_t o = lw + (size_t)(n0 + ni) * K + k0 + tx;
        hi[o] = h;
        lo[o] = __float2bfloat16_rn(v - __bfloat162float(h));
    }
}

// ============================ mma.sync bf16x3 GEMM (templated tile-M) ============================
template<int EPI, int TM>  // EPI: 0 fp32 out; 2 bf16 hi/lo out; 3 GELU + bf16 hi/lo out
__global__ void __launch_bounds__(256) mma_gemm_kernel(
    const __nv_bfloat16* __restrict__ Ahi, const __nv_bfloat16* __restrict__ Alo,
    const __nv_bfloat16* __restrict__ Bhi, const __nv_bfloat16* __restrict__ Blo,
    const float* __restrict__ bias, float* __restrict__ C,
    __nv_bfloat16* __restrict__ Chi, __nv_bfloat16* __restrict__ Clo, int N, int K)
{
    constexpr int MBN   = TM / 64;                  // m-blocks per warp
    constexpr int ABYTES = TM * 128;                // one A matrix per stage
    constexpr int STAGE  = 2 * ABYTES + 32768;
    extern __shared__ char smem[];
    const int tid  = threadIdx.x;
    const int lane = tid & 31;
    const int wid  = tid >> 5;
    const int m0 = blockIdx.y * TM, n0 = blockIdx.x * 128;
    const int wrow = (wid >> 1) * (16 * MBN);
    const int wcol = (wid & 1) * 64;
    const uint32_t sbase = smem_to_u32(smem);

    float acc[MBN][8][4];
    #pragma unroll
    for (int a = 0; a < MBN; a++)
        #pragma unroll
        for (int b = 0; b < 8; b++)
            #pragma unroll
            for (int c = 0; c < 4; c++) acc[a][b][c] = 0.f;

    const int nc = K >> 6;

    auto loadChunk = [&](int c) {
        uint32_t sb = sbase + (uint32_t)(c & 1) * STAGE;
        int k0 = c << 6;
        // A hi/lo: TM rows
        #pragma unroll
        for (int t2 = 0; t2 < 2; t2++) {
            const __nv_bfloat16* s = t2 ? Alo : Ahi;
            #pragma unroll
            for (int it = 0; it < TM / 32; it++) {
                int idx = it * 256 + tid;
                int row = idx >> 3, ch = idx & 7;
                CP_ASYNC16(sb + t2 * ABYTES + ASM_OFF(row, ch),
                           s + (size_t)(m0 + row) * K + k0 + ch * 8);
            }
        }
        // B hi/lo: 128 rows
        #pragma unroll
        for (int t2 = 0; t2 < 2; t2++) {
            const __nv_bfloat16* s = t2 ? Blo : Bhi;
            #pragma unroll
            for (int it = 0; it < 4; it++) {
                int idx = it * 256 + tid;
                int row = idx >> 3, ch = idx & 7;
                CP_ASYNC16(sb + 2 * ABYTES + t2 * 16384 + ASM_OFF(row, ch),
                           s + (size_t)(n0 + row) * K + k0 + ch * 8);
            }
        }
        CP_COMMIT();
    };

    loadChunk(0);
    if (nc > 1) loadChunk(1);

    for (int c = 0; c < nc; c++) {
        if (c + 1 < nc) CP_WAIT1(); else CP_WAIT0();
        __syncthreads();
        uint32_t sb = sbase + (uint32_t)(c & 1) * STAGE;
        uint32_t sAh = sb, sAl = sb + ABYTES, sBh = sb + 2 * ABYTES, sBl = sb + 2 * ABYTES + 16384;
        #pragma unroll
        for (int ks = 0; ks < 4; ks++) {
            uint32_t ah[MBN][4], al[MBN][4], bh[4][4], bl[4][4];
            {
                int sub = lane >> 3;
                int row16 = (lane & 7) + ((sub & 1) << 3);
                int kc = ks * 2 + (sub >> 1);
                #pragma unroll
                for (int mb = 0; mb < MBN; mb++) {
                    int row = wrow + mb * 16 + row16;
                    uint32_t off = ASM_OFF(row, kc);
                    ldsm4(ah[mb], sAh + off);
                    ldsm4(al[mb], sAl + off);
                }
            }
            {
                int sub = lane >> 3;
                int kc = ks * 2 + (sub & 1);
                int nr = ((sub >> 1) << 3) + (lane & 7);
                #pragma unroll
                for (int j = 0; j < 4; j++) {
                    int row = wcol + j * 16 + nr;
                    uint32_t off = ASM_OFF(row, kc);
                    ldsm4(bh[j], sBh + off);
                    ldsm4(bl[j], sBl + off);
                }
            }
            #pragma unroll
            for (int mb = 0; mb < MBN; mb++)
                #pragma unroll
                for (int j = 0; j < 4; j++) {
                    mma16816(acc[mb][2*j],     ah[mb], &bh[j][0]);
                    mma16816(acc[mb][2*j],     ah[mb], &bl[j][0]);
                    mma16816(acc[mb][2*j],     al[mb], &bh[j][0]);
                    mma16816(acc[mb][2*j + 1], ah[mb], &bh[j][2]);
                    mma16816(acc[mb][2*j + 1], ah[mb], &bl[j][2]);
                    mma16816(acc[mb][2*j + 1], al[mb], &bh[j][2]);
                }
        }
        __syncthreads();
        if (c + 2 < nc) loadChunk(c + 2);
    }

    const int r_l = lane >> 2;
    const int c_l = (lane & 3) << 1;
    #pragma unroll
    for (int mb = 0; mb < MBN; mb++) {
        #pragma unroll
        for (int nb = 0; nb < 8; nb++) {
            int row = m0 + wrow + mb * 16 + r_l;
            int col = n0 + wcol + nb * 8 + c_l;
            float b0 = bias[col], b1 = bias[col + 1];
            float v0 = acc[mb][nb][0] + b0;
            float v1 = acc[mb][nb][1] + b1;
            float v2 = acc[mb][nb][2] + b0;
            float v3 = acc[mb][nb][3] + b1;
            if (EPI == 3) {
                v0 = 0.5f * v0 * (1.f + erff(v0 * 0.70710678118654752f));
                v1 = 0.5f * v1 * (1.f + erff(v1 * 0.70710678118654752f));
                v2 = 0.5f * v2 * (1.f + erff(v2 * 0.70710678118654752f));
                v3 = 0.5f * v3 * (1.f + erff(v3 * 0.70710678118654752f));
            }
            if (EPI == 0) {
                *reinterpret_cast<float2*>(C + (size_t)row * N + col)       = make_float2(v0, v1);
                *reinterpret_cast<float2*>(C + (size_t)(row + 8) * N + col) = make_float2(v2, v3);
            } else {
                __nv_bfloat162 h01 = __floats2bfloat162_rn(v0, v1);
                __nv_bfloat162 h23 = __floats2bfloat162_rn(v2, v3);
                __nv_bfloat162 l01 = __floats2bfloat162_rn(v0 - __bfloat162float(h01.x),
                                                           v1 - __bfloat162float(h01.y));
                __nv_bfloat162 l23 = __floats2bfloat162_rn(v2 - __bfloat162float(h23.x),
                                                           v3 - __bfloat162float(h23.y));
                *reinterpret_cast<__nv_bfloat162*>(Chi + (size_t)row * N + col)       = h01;
                *reinterpret_cast<__nv_bfloat162*>(Chi + (size_t)(row + 8) * N + col) = h23;
                *reinterpret_cast<__nv_bfloat162*>(Clo + (size_t)row * N + col)       = l01;
                *reinterpret_cast<__nv_bfloat162*>(Clo + (size_t)(row + 8) * N + col) = l23;
            }
        }
    }
}

// ============================ tensor-core attention ============================
#define AT_QH 0
#define AT_QL 16384
#define AT_KH 32768
#define AT_KL 40960
#define AT_VH 49152
#define AT_VL 57344
#define AT_BS 65536
#define AT_SMEM (65536 + 256)

__global__ void __launch_bounds__(128) attn_tc_kernel(
    const __nv_bfloat16* __restrict__ qh, const __nv_bfloat16* __restrict__ ql,
    const float* __restrict__ pep, float* __restrict__ part, float* __restrict__ plsum)
{
    extern __shared__ char sm[];
    const int h = blockIdx.y, sl = blockIdx.z;
    const int q0 = blockIdx.x * 128;
    const int tid = threadIdx.x, lane = tid & 31, wid = tid >> 5;
    const int wrow = wid * 32;
    const int sub = lane >> 3;
    const uint32_t sb = smem_to_u32(sm);
    float* bias = reinterpret_cast<float*>(sm + AT_BS);

    #pragma unroll
    for (int it = 0; it < 8; it++) {
        int idx = it * 128 + tid;
        int row = idx >> 3, ch = idx & 7;
        size_t g = (size_t)(q0 + row) * 1536 + h * 64 + ch * 8;
        uint32_t off = ASM_OFF(row, ch);
        CP_ASYNC16(sb + AT_QH + off, qh + g);
        CP_ASYNC16(sb + AT_QL + off, ql + g);
    }
    CP_COMMIT();

    float O[2][8][4];
    float ls[2][2] = {{0.f, 0.f}, {0.f, 0.f}};
    #pragma unroll
    for (int mb = 0; mb < 2; mb++)
        #pragma unroll
        for (int nb = 0; nb < 8; nb++)
            #pragma unroll
            for (int u = 0; u < 4; u++) O[mb][nb][u] = 0.f;

    for (int c = 0; c < 8; c++) {
        const int kk = sl * 512 + c * 64;
        #pragma unroll
        for (int it = 0; it < 4; it++) {
            int idx = it * 128 + tid;
            int row = idx >> 3, ch = idx & 7;
            size_t gk = (size_t)(kk + row) * 1536 + 512 + h * 64 + ch * 8;
            uint32_t off = ASM_OFF(row, ch);
            CP_ASYNC16(sb + AT_KH + off, qh + gk);
            CP_ASYNC16(sb + AT_KL + off, ql + gk);
            CP_ASYNC16(sb + AT_VH + off, qh + gk + 512);
            CP_ASYNC16(sb + AT_VL + off, ql + gk + 512);
        }
        if (tid < 64) bias[tid] = pep[(size_t)(kk + tid) * HH + h];
        CP_COMMIT();
        CP_WAIT0();
        __syncthreads();

        float S[2][8][4];
        #pragma unroll
        for (int mb = 0; mb < 2; mb++)
            #pragma unroll
            for (int nb = 0; nb < 8; nb++)
                #pragma unroll
                for (int u = 0; u < 4; u++) S[mb][nb][u] = 0.f;
        #pragma unroll
        for (int kb = 0; kb < 4; kb++) {
            uint32_t ah[2][4], al[2][4];
            int r16 = (lane & 7) + ((sub & 1) << 3);
            int chA = kb * 2 + (sub >> 1);
            #pragma unroll
            for (int mb = 0; mb < 2; mb++) {
                int row = wrow + mb * 16 + r16;
                uint32_t off = ASM_OFF(row, chA);
                ldsm4(ah[mb], sb + AT_QH + off);
                ldsm4(al[mb], sb + AT_QL + off);
            }
            int chB = kb * 2 + (sub & 1);
            int nr = ((sub >> 1) << 3) + (lane & 7);
            #pragma unroll
            for (int j = 0; j < 4; j++) {
                uint32_t bh[4], bl[4];
                int row = j * 16 + nr;
                uint32_t off = ASM_OFF(row, chB);
                ldsm4(bh, sb + AT_KH + off);
                ldsm4(bl, sb + AT_KL + off);
                #pragma unroll
                for (int mb = 0; mb < 2; mb++) {
                    mma16816(S[mb][2*j],   ah[mb], &bh[0]);
                    mma16816(S[mb][2*j],   al[mb], &bh[0]);
                    mma16816(S[mb][2*j],   ah[mb], &bl[0]);
                    mma16816(S[mb][2*j+1], ah[mb], &bh[2]);
                    mma16816(S[mb][2*j+1], al[mb], &bh[2]);
                    mma16816(S[mb][2*j+1], ah[mb], &bl[2]);
                }
            }
        }

        uint32_t Ph[2][8][2], Pl[2][8][2];
        #pragma unroll
        for (int mb = 0; mb < 2; mb++)
            #pragma unroll
            for (int nb = 0; nb < 8; nb++) {
                int col = nb * 8 + ((lane & 3) << 1);
                float b0 = bias[col], b1 = bias[col + 1];
                float p0 = __expf(fmaf(S[mb][nb][0], 0.125f, -b0));
                float p1 = __expf(fmaf(S[mb][nb][1], 0.125f, -b1));
                float p2 = __expf(fmaf(S[mb][nb][2], 0.125f, -b0));
                float p3 = __expf(fmaf(S[mb][nb][3], 0.125f, -b1));
                ls[mb][0] += p0 + p1;
                ls[mb][1] += p2 + p3;
                __nv_bfloat162 h01 = __floats2bfloat162_rn(p0, p1);
                __nv_bfloat162 h23 = __floats2bfloat162_rn(p2, p3);
                __nv_bfloat162 l01 = __floats2bfloat162_rn(p0 - __bfloat162float(h01.x),
                                                           p1 - __bfloat162float(h01.y));
                __nv_bfloat162 l23 = __floats2bfloat162_rn(p2 - __bfloat162float(h23.x),
                                                           p3 - __bfloat162float(h23.y));
                Ph[mb][nb][0] = *reinterpret_cast<uint32_t*>(&h01);
                Ph[mb][nb][1] = *reinterpret_cast<uint32_t*>(&h23);
                Pl[mb][nb][0] = *reinterpret_cast<uint32_t*>(&l01);
                Pl[mb][nb][1] = *reinterpret_cast<uint32_t*>(&l23);
            }

        #pragma unroll
        for (int kb2 = 0; kb2 < 4; kb2++) {
            int krow = kb2 * 16 + ((sub & 1) << 3) + (lane & 7);
            #pragma unroll
            for (int dI = 0; dI < 4; dI++) {
                uint32_t vh[4], vl[4];
                int ch = dI * 2 + (sub >> 1);
                uint32_t off = ASM_OFF(krow, ch);
                ldsm4t(vh, sb + AT_VH + off);
                ldsm4t(vl, sb + AT_VL + off);
                #pragma unroll
                for (int mb = 0; mb < 2; mb++) {
                    uint32_t pa[4] = {Ph[mb][2*kb2][0], Ph[mb][2*kb2][1],
                                      Ph[mb][2*kb2+1][0], Ph[mb][2*kb2+1][1]};
                    uint32_t la[4] = {Pl[mb][2*kb2][0], Pl[mb][2*kb2][1],
                                      Pl[mb][2*kb2+1][0], Pl[mb][2*kb2+1][1]};
                    mma16816(O[mb][2*dI],   pa, &vh[0]);
                    mma16816(O[mb][2*dI],   la, &vh[0]);
                    mma16816(O[mb][2*dI],   pa, &vl[0]);
                    mma16816(O[mb][2*dI+1], pa, &vh[2]);
                    mma16816(O[mb][2*dI+1], la, &vh[2]);
                    mma16816(O[mb][2*dI+1], pa, &vl[2]);
                }
            }
        }
        __syncthreads();
    }

    #pragma unroll
    for (int mb = 0; mb < 2; mb++)
        #pragma unroll
        for (int r = 0; r < 2; r++) {
            float v = ls[mb][r];
            v += __shfl_xor_sync(0xffffffffu, v, 1);
            v += __shfl_xor_sync(0xffffffffu, v, 2);
            ls[mb][r] = v;
        }
    const size_t base = (size_t)(sl * HH + h) * NN;
    #pragma unroll
    for (int mb = 0; mb < 2; mb++) {
        int rowA = q0 + wrow + mb * 16 + (lane >> 2);
        int rowB = rowA + 8;
        if ((lane & 3) == 0) {
            plsum[base + rowA] = ls[mb][0];
            plsum[base + rowB] = ls[mb][1];
        }
        #pragma unroll
        for (int nb = 0; nb < 8; nb++) {
            int col = nb * 8 + ((lane & 3) << 1);
            *reinterpret_cast<float2*>(part + (base + rowA) * 64 + col) = make_float2(O[mb][nb][0], O[mb][nb][1]);
            *reinterpret_cast<float2*>(part + (base + rowB) * 64 + col) = make_float2(O[mb][nb][2], O[mb][nb][3]);
        }
    }
}

__global__ void attn_combine_kernel(const float* __restrict__ part, const float* __restrict__ pls,
                                    __nv_bfloat16* __restrict__ ohi, __nv_bfloat16* __restrict__ olo) {
    int i = blockIdx.x, t = threadIdx.x;
    #pragma unroll
    for (int rep = 0; rep < 2; rep++) {
        int idx = t + rep * 256;
        int h = idx >> 6, d = idx & 63;
        float v = 0.f, l = 0.f;
        #pragma unroll
        for (int s = 0; s < 4; s++) {
            l += pls[(size_t)(s * HH + h) * NN + i];
            v += part[((size_t)(s * HH + h) * NN + i) * 64 + d];
        }
        float r = v / l;
        __nv_bfloat16 hb = __float2bfloat16_rn(r);
        ohi[(size_t)i * DD + idx] = hb;
        olo[(size_t)i * DD + idx] = __float2bfloat16_rn(r - __bfloat162float(hb));
    }
}

// ============================ LN (fp32 out + bf16 hi/lo) ============================
__global__ void ln_kernel(const float* __restrict__ a, const float* __restrict__ b,
                          const float* __restrict__ g, const float* __restrict__ be,
                          float* __restrict__ out,
                          __nv_bfloat16* __restrict__ ohi, __nv_bfloat16* __restrict__ olo) {
    __shared__ float sh[256];
    __shared__ float s_mu, s_r;
    int i = blockIdx.x, t = threadIdx.x;
    float v0 = a[(size_t)i * DD + t]       + b[(size_t)i * DD + t];
    float v1 = a[(size_t)i * DD + 256 + t] + b[(size_t)i * DD + 256 + t];
    sh[t] = v0 + v1; __syncthreads();
    for (int k = 128; k > 0; k >>= 1) { if (t < k) sh[t] += sh[t + k]; __syncthreads(); }
    if (t == 0) s_mu = sh[0] * (1.f / DD);
    __syncthreads();
    float mu = s_mu;
    float d0 = v0 - mu, d1 = v1 - mu;
    sh[t] = d0 * d0 + d1 * d1; __syncthreads();
    for (int k = 128; k > 0; k >>= 1) { if (t < k) sh[t] += sh[t + k]; __syncthreads(); }
    if (t == 0) s_r = rsqrtf(sh[0] * (1.f / DD) + 1e-5f);
    __syncthreads();
    float r = s_r;
    float o0 = d0 * r * g[t]       + be[t];
    float o1 = d1 * r * g[256 + t] + be[256 + t];
    out[(size_t)i * DD + t]       = o0;
    out[(size_t)i * DD + 256 + t] = o1;
    __nv_bfloat16 h0 = __float2bfloat16_rn(o0);
    __nv_bfloat16 h1 = __float2bfloat16_rn(o1);
    ohi[(size_t)i * DD + t]       = h0;
    ohi[(size_t)i * DD + 256 + t] = h1;
    olo[(size_t)i * DD + t]       = __float2bfloat16_rn(o0 - __bfloat162float(h0));
    olo[(size_t)i * DD + 256 + t] = __float2bfloat16_rn(o1 - __bfloat162float(h1));
}

// ============================ launch ============================
extern "C" void kernel_launch(void* const* d_in, const int* in_sizes, int n_in,
                              void* d_out, int out_size) {
    const float* node_features = (const float*)d_in[0];
    const int*   edge_index    = (const int*)  d_in[1];
    const float* pe_proj_W     = (const float*)d_in[2];
    const float* pe_proj_b     = (const float*)d_in[3];
    const float* qkv_W         = (const float*)d_in[4];
    const float* qkv_b         = (const float*)d_in[5];
    const float* peb_W         = (const float*)d_in[6];
    const float* peb_b         = (const float*)d_in[7];
    const float* out_W         = (const float*)d_in[8];
    const float* out_b         = (const float*)d_in[9];
    const float* ffn_W1        = (const float*)d_in[10];
    const float* ffn_b1        = (const float*)d_in[11];
    const float* ffn_W2        = (const float*)d_in[12];
    const float* ffn_b2        = (const float*)d_in[13];
    const float* ln1_g         = (const float*)d_in[14];
    const float* ln1_b         = (const float*)d_in[15];
    const float* ln2_g         = (const float*)d_in[16];
    const float* ln2_b         = (const float*)d_in[17];
    float* outp = (float*)d_out;

    float *x_, *x1_, *o_, *pep_, *part_, *pls_;
    __nv_bfloat16 *Ahi_, *Alo_, *Hhi_, *Hlo_, *Qh_, *Ql_, *T2b_, *T3b_, *T4b_;
    __nv_bfloat16 *qWh_, *qWl_, *oWh_, *oWl_, *f1h_, *f1l_, *f2h_, *f2l_;
    cudaGetSymbolAddress((void**)&x_,   g_x);
    cudaGetSymbolAddress((void**)&x1_,  g_x1);
    cudaGetSymbolAddress((void**)&o_,   g_o);
    cudaGetSymbolAddress((void**)&pep_, g_pep);
    cudaGetSymbolAddress((void**)&part_,g_part);
    cudaGetSymbolAddress((void**)&pls_, g_plsum);
    cudaGetSymbolAddress((void**)&Ahi_, g_Ahi);
    cudaGetSymbolAddress((void**)&Alo_, g_Alo);
    cudaGetSymbolAddress((void**)&Hhi_, g_Hhi);
    cudaGetSymbolAddress((void**)&Hlo_, g_Hlo);
    cudaGetSymbolAddress((void**)&Qh_,  g_QKVhi);
    cudaGetSymbolAddress((void**)&Ql_,  g_QKVlo);
    cudaGetSymbolAddress((void**)&T2b_, g_T2b);
    cudaGetSymbolAddress((void**)&T3b_, g_T3b);
    cudaGetSymbolAddress((void**)&T4b_, g_T4b);
    cudaGetSymbolAddress((void**)&qWh_, g_qkvW_hi);
    cudaGetSymbolAddress((void**)&qWl_, g_qkvW_lo);
    cudaGetSymbolAddress((void**)&oWh_, g_outW_hi);
    cudaGetSymbolAddress((void**)&oWl_, g_outW_lo);
    cudaGetSymbolAddress((void**)&f1h_, g_f1W_hi);
    cudaGetSymbolAddress((void**)&f1l_, g_f1W_lo);
    cudaGetSymbolAddress((void**)&f2h_, g_f2W_hi);
    cudaGetSymbolAddress((void**)&f2l_, g_f2W_lo);

    constexpr int GS128 = 2 * (2 * 128 * 128 + 32768);   // 131072
    constexpr int GS64  = 2 * (2 * 64  * 128 + 32768);   // 98304
    cudaFuncSetAttribute(mma_gemm_kernel<2,128>, cudaFuncAttributeMaxDynamicSharedMemorySize, GS128);
    cudaFuncSetAttribute(mma_gemm_kernel<3,128>, cudaFuncAttributeMaxDynamicSharedMemorySize, GS128);
    cudaFuncSetAttribute(mma_gemm_kernel<0,64>,  cudaFuncAttributeMaxDynamicSharedMemorySize, GS64);
    cudaFuncSetAttribute(attn_tc_kernel, cudaFuncAttributeMaxDynamicSharedMemorySize, AT_SMEM);

    // ---- weight conversion (layer-batched) ----
    convW_kernel<<<dim3(1536/32, 512/32, LLC),  dim3(32,8)>>>(qkv_W,  qWh_, qWl_, DD,  3*DD);
    convW_kernel<<<dim3(512/32,  512/32, LLC),  dim3(32,8)>>>(out_W,  oWh_, oWl_, DD,  DD);
    convW_kernel<<<dim3(2048/32, 512/32, LLC),  dim3(32,8)>>>(ffn_W1, f1h_, f1l_, DD,  DFFC);
    convW_kernel<<<dim3(512/32,  2048/32, LLC), dim3(32,8)>>>(ffn_W2, f2h_, f2l_, DFFC, DD);

    // ---- PE pipeline (sparse) ----
    zero_bm_kernel<<<(NN*64)/256, 256>>>();
    scatter_bm_kernel<<<EEC/256, 256>>>(edge_index);
    build_bm_kernel<<<NN, 64>>>();
    t2_kernel<<<NN, 256>>>();
    spmm_bf_kernel<<<NN, 256>>>(T2b_, T3b_);
    spmm_bf_kernel<<<NN, 256>>>(T3b_, T4b_);
    diag2_kernel<<<NN, 256>>>();
    pe_kernel<<<(NN + 127) / 128, 128>>>(pe_proj_W, pe_proj_b);
    pep_kernel<<<(NN + 127) / 128, 128>>>(peb_W, peb_b);

    // ---- transformer ----
    split_copy_kernel<<<(NN*DD)/256, 256>>>(node_features);
    for (int l = 0; l < LLC; l++) {
        mma_gemm_kernel<2,128><<<dim3(1536/128, NN/128), 256, GS128>>>(
            Ahi_, Alo_, qWh_ + (size_t)l*3*DD*DD, qWl_ + (size_t)l*3*DD*DD,
            qkv_b + (size_t)l*3*DD, nullptr, Qh_, Ql_, 3*DD, DD);
        attn_tc_kernel<<<dim3(NN/128, HH, 4), 128, AT_SMEM>>>(Qh_, Ql_, pep_ + (size_t)l*NN*HH, part_, pls_);
        attn_combine_kernel<<<NN, 256>>>(part_, pls_, Ahi_, Alo_);
        mma_gemm_kernel<0,64><<<dim3(DD/128, NN/64), 256, GS64>>>(
            Ahi_, Alo_, oWh_ + (size_t)l*DD*DD, oWl_ + (size_t)l*DD*DD,
            out_b + (size_t)l*DD, o_, nullptr, nullptr, DD, DD);
        ln_kernel<<<NN, 256>>>(x_, o_, ln1_g + (size_t)l*DD, ln1_b + (size_t)l*DD, x1_, Ahi_, Alo_);
        mma_gemm_kernel<3,128><<<dim3(DFFC/128, NN/128), 256, GS128>>>(
            Ahi_, Alo_, f1h_ + (size_t)l*DD*DFFC, f1l_ + (size_t)l*DD*DFFC,
            ffn_b1 + (size_t)l*DFFC, nullptr, Hhi_, Hlo_, DFFC, DD);
        mma_gemm_kernel<0,64><<<dim3(DD/128, NN/64), 256, GS64>>>(
            Hhi_, Hlo_, f2h_ + (size_t)l*DFFC*DD, f2l_ + (size_t)l*DFFC*DD,
            ffn_b2 + (size_t)l*DD, o_, nullptr, nullptr, DD, DFFC);
        float* xout = (l == LLC - 1) ? outp : x_;
        ln_kernel<<<NN, 256>>>(x1_, o_, ln2_g + (size_t)l*DD, ln2_b + (size_t)l*DD, xout, Ahi_, Alo_);
    }
}

// round 6
// speedup vs baseline: 5.0197x; 1.0272x over previous
#include <cuda_runtime.h>
#include <cuda_bf16.h>
#include <math.h>
#include <stdint.h>

#define NN   2048
#define DD   512
#define HH   8
#define DPEC 16
#define WALKC 8
#define LLC  3
#define EEC  32768
#define DFFC 2048
#define MAXD 256

// ============================ PTX helpers (sm_80-baseline ISA only) ============================
__device__ __forceinline__ uint32_t smem_to_u32(const void* p) {
    uint32_t a;
    asm("{ .reg .u64 t; cvta.to.shared.u64 t, %1; cvt.u32.u64 %0, t; }" : "=r"(a) : "l"(p));
    return a;
}
#define CP_ASYNC16(dst, src) \
    asm volatile("cp.async.cg.shared.global [%0], [%1], 16;" :: "r"(dst), "l"(src))
#define CP_COMMIT() asm volatile("cp.async.commit_group;" ::: "memory")
#define CP_WAIT1()  asm volatile("cp.async.wait_group 1;" ::: "memory")
#define CP_WAIT0()  asm volatile("cp.async.wait_group 0;" ::: "memory")

__device__ __forceinline__ void ldsm4(uint32_t* r, uint32_t addr) {
    asm volatile("ldmatrix.sync.aligned.m8n8.x4.shared.b16 {%0,%1,%2,%3}, [%4];"
        : "=r"(r[0]), "=r"(r[1]), "=r"(r[2]), "=r"(r[3]) : "r"(addr));
}
__device__ __forceinline__ void ldsm4t(uint32_t* r, uint32_t addr) {
    asm volatile("ldmatrix.sync.aligned.m8n8.x4.trans.shared.b16 {%0,%1,%2,%3}, [%4];"
        : "=r"(r[0]), "=r"(r[1]), "=r"(r[2]), "=r"(r[3]) : "r"(addr));
}
__device__ __forceinline__ void mma16816(float* c, const uint32_t* a, const uint32_t* b) {
    asm volatile("mma.sync.aligned.m16n8k16.row.col.f32.bf16.bf16.f32 "
        "{%0,%1,%2,%3}, {%4,%5,%6,%7}, {%8,%9}, {%0,%1,%2,%3};"
        : "+f"(c[0]), "+f"(c[1]), "+f"(c[2]), "+f"(c[3])
        : "r"(a[0]), "r"(a[1]), "r"(a[2]), "r"(a[3]), "r"(b[0]), "r"(b[1]));
}

#define ASM_OFF(row, ch) ((uint32_t)((row) * 128 + ((((ch)) ^ ((row) & 7)) << 4)))

// ============================ static device scratch ============================
__device__ uint32_t g_bm[NN*64];
__device__ float g_deg[NN];
__device__ float g_invdeg[NN];
__device__ int   g_nbr[NN*MAXD];
__device__ int   g_cnt[NN];
__device__ __nv_bfloat16 g_T2b[NN*NN];
__device__ __nv_bfloat16 g_T3b[NN*NN];
__device__ __nv_bfloat16 g_T4b[NN*NN];
__device__ float g_rw [NN*WALKC];
__device__ float g_pe [NN*DPEC];
__device__ float g_pep[LLC*NN*HH];
__device__ float g_x   [NN*DD];
__device__ float g_x1  [NN*DD];
__device__ float g_o   [NN*DD];
__device__ __nv_bfloat16 g_Ahi[NN*DD];
__device__ __nv_bfloat16 g_Alo[NN*DD];
__device__ __nv_bfloat16 g_Hhi[NN*DFFC];
__device__ __nv_bfloat16 g_Hlo[NN*DFFC];
__device__ __nv_bfloat16 g_QKVhi[NN*3*DD];
__device__ __nv_bfloat16 g_QKVlo[NN*3*DD];
__device__ __nv_bfloat16 g_qkvW_hi[LLC*3*DD*DD];
__device__ __nv_bfloat16 g_qkvW_lo[LLC*3*DD*DD];
__device__ __nv_bfloat16 g_outW_hi[LLC*DD*DD];
__device__ __nv_bfloat16 g_outW_lo[LLC*DD*DD];
__device__ __nv_bfloat16 g_f1W_hi[LLC*DD*DFFC];
__device__ __nv_bfloat16 g_f1W_lo[LLC*DD*DFFC];
__device__ __nv_bfloat16 g_f2W_hi[LLC*DFFC*DD];
__device__ __nv_bfloat16 g_f2W_lo[LLC*DFFC*DD];
__device__ float g_part [4*HH*NN*64];
__device__ float g_plsum[4*HH*NN];

// ============================ PE pipeline (sparse) ============================
__global__ void zero_bm_kernel() {
    int idx = blockIdx.x * blockDim.x + threadIdx.x;
    if (idx < NN * 64) g_bm[idx] = 0u;
}
__global__ void scatter_bm_kernel(const int* __restrict__ ei) {
    int e = blockIdx.x * blockDim.x + threadIdx.x;
    if (e < EEC) {
        int s = ei[e], t = ei[EEC + e];
        atomicOr(&g_bm[s * 64 + (t >> 5)], 1u << (t & 31));
        atomicOr(&g_bm[t * 64 + (s >> 5)], 1u << (s & 31));
    }
}
__global__ void build_bm_kernel() {
    __shared__ int cnt;
    int i = blockIdx.x, t = threadIdx.x;
    if (t == 0) cnt = 0;
    __syncthreads();
    uint32_t w = g_bm[i * 64 + t];
    int c = __popc(w);
    int pos = (c > 0) ? atomicAdd(&cnt, c) : 0;
    while (w) {
        int b = __ffs(w) - 1;
        w &= w - 1;
        if (pos < MAXD) g_nbr[i * MAXD + pos] = t * 32 + b;
        pos++;
    }
    __syncthreads();
    if (t == 0) {
        int cc = cnt < MAXD ? cnt : MAXD;
        g_cnt[i] = cc;
        float d = cnt < 1 ? 1.f : (float)cnt;
        g_deg[i] = d;
        g_invdeg[i] = 1.f / d;
    }
}
__global__ void __launch_bounds__(256) t2_kernel() {
    __shared__ float rowbuf[NN];
    int i = blockIdx.x, t = threadIdx.x;
    #pragma unroll
    for (int u = 0; u < NN / 256; u++) rowbuf[t + u * 256] = 0.f;
    __syncthreads();
    int cnt = g_cnt[i];
    float inv_i = g_invdeg[i];
    for (int c = t >> 3; c < cnt; c += 32) {
        int j = g_nbr[i * MAXD + c];
        float w = inv_i * g_invdeg[j];
        int cj = g_cnt[j];
        const int* nbj = g_nbr + j * MAXD;
        for (int k = t & 7; k < cj; k += 8) atomicAdd(&rowbuf[nbj[k]], w);
    }
    __syncthreads();
    __nv_bfloat16* out = g_T2b + (size_t)i * NN;
    #pragma unroll
    for (int u = 0; u < NN / 256; u++) {
        int idx = t + u * 256;
        out[idx] = __float2bfloat16_rn(rowbuf[idx]);
    }
}
__global__ void __launch_bounds__(256) spmm_bf_kernel(const __nv_bfloat16* __restrict__ IN,
                                                      __nv_bfloat16* __restrict__ OUT) {
    int i = blockIdx.x, t = threadIdx.x;
    int cnt = g_cnt[i];
    float inv = g_invdeg[i];
    const int* nb = g_nbr + i * MAXD;
    float2 acc[4];
    #pragma unroll
    for (int u = 0; u < 4; u++) acc[u] = make_float2(0.f, 0.f);
    for (int c = 0; c < cnt; c++) {
        const __nv_bfloat162* row = reinterpret_cast<const __nv_bfloat162*>(IN + (size_t)nb[c] * NN);
        #pragma unroll
        for (int u = 0; u < 4; u++) {
            float2 v = __bfloat1622float2(row[t + u * 256]);
            acc[u].x += v.x; acc[u].y += v.y;
        }
    }
    __nv_bfloat162* out = reinterpret_cast<__nv_bfloat162*>(OUT + (size_t)i * NN);
    #pragma unroll
    for (int u = 0; u < 4; u++)
        out[t + u * 256] = __floats2bfloat162_rn(acc[u].x * inv, acc[u].y * inv);
}
__global__ void diag2_kernel() {
    __shared__ float sh[256];
    __shared__ float res[7];
    int i = blockIdx.x, t = threadIdx.x;
    float inv_i = g_invdeg[i], d_i = g_deg[i];
    int cnt = g_cnt[i];
    const __nv_bfloat16* r2 = g_T2b + (size_t)i * NN;
    const __nv_bfloat16* r3 = g_T3b + (size_t)i * NN;
    const __nv_bfloat16* r4 = g_T4b + (size_t)i * NN;
    float s[7] = {};
    for (int c = t; c < cnt; c += 256) {
        int j = g_nbr[i * MAXD + c];
        float wj = g_invdeg[j];
        s[0] += wj;
        s[1] += __bfloat162float(r2[j]) * wj;
    }
    for (int j = t; j < NN; j += 256) {
        float w = g_invdeg[j];
        float t2 = __bfloat162float(r2[j]);
        float t3 = __bfloat162float(r3[j]);
        float t4 = __bfloat162float(r4[j]);
        s[2] += t2 * t2 * w;
        s[3] += t3 * t2 * w;
        s[4] += t3 * t3 * w;
        s[5] += t4 * t3 * w;
        s[6] += t4 * t4 * w;
    }
    for (int v = 0; v < 7; v++) {
        sh[t] = s[v]; __syncthreads();
        for (int k = 128; k > 0; k >>= 1) { if (t < k) sh[t] += sh[t + k]; __syncthreads(); }
        if (t == 0) res[v] = sh[0];
        __syncthreads();
    }
    if (t == 0) {
        bool self = (g_bm[i * 64 + (i >> 5)] >> (i & 31)) & 1u;
        g_rw[i * WALKC + 0] = self ? inv_i : 0.f;
        g_rw[i * WALKC + 1] = inv_i * res[0];
        g_rw[i * WALKC + 2] = res[1];
        g_rw[i * WALKC + 3] = d_i * res[2];
        g_rw[i * WALKC + 4] = d_i * res[3];
        g_rw[i * WALKC + 5] = d_i * res[4];
        g_rw[i * WALKC + 6] = d_i * res[5];
        g_rw[i * WALKC + 7] = d_i * res[6];
    }
}
__global__ void pe_kernel(const float* __restrict__ W, const float* __restrict__ b) {
    int i = blockIdx.x * blockDim.x + threadIdx.x;
    if (i >= NN) return;
    float r[WALKC];
    #pragma unroll
    for (int w = 0; w < WALKC; w++) r[w] = g_rw[i * WALKC + w];
    #pragma unroll
    for (int d = 0; d < DPEC; d++) {
        float s = b[d];
        #pragma unroll
        for (int w = 0; w < WALKC; w++) s += r[w] * W[w * DPEC + d];
        g_pe[i * DPEC + d] = s;
    }
}
__global__ void pep_kernel(const float* __restrict__ W, const float* __restrict__ b) {
    int i = blockIdx.x * blockDim.x + threadIdx.x;
    if (i >= NN) return;
    float p[DPEC];
    #pragma unroll
    for (int d = 0; d < DPEC; d++) p[d] = g_pe[i * DPEC + d];
    for (int l = 0; l < LLC; l++) {
        #pragma unroll
        for (int h = 0; h < HH; h++) {
            float s = b[l * HH + h];
            #pragma unroll
            for (int d = 0; d < DPEC; d++) s += p[d] * W[(l * DPEC + d) * HH + h];
            g_pep[(size_t)l * NN * HH + i * HH + h] = s;
        }
    }
}

// ============================ conversions ============================
__global__ void split_copy_kernel(const float* __restrict__ src) {
    int idx = blockIdx.x * blockDim.x + threadIdx.x;
    if (idx < NN * DD) {
        float v = src[idx];
        g_x[idx] = v;
        __nv_bfloat16 h = __float2bfloat16_rn(v);
        g_Ahi[idx] = h;
        g_Alo[idx] = __float2bfloat16_rn(v - __bfloat162float(h));
    }
}
__global__ void convW_kernel(const float* __restrict__ W, __nv_bfloat16* __restrict__ hi,
                             __nv_bfloat16* __restrict__ lo, int K, int N) {
    __shared__ float tile[32][33];
    size_t lw = (size_t)blockIdx.z * K * N;
    int n0 = blockIdx.x * 32, k0 = blockIdx.y * 32;
    int tx = threadIdx.x, ty = threadIdx.y;
    #pragma unroll
    for (int r = 0; r < 4; r++)
        tile[ty + r * 8][tx] = W[lw + (size_t)(k0 + ty + r * 8) * N + n0 + tx];
    __syncthreads();
    #pragma unroll
    for (int r = 0; r < 4; r++) {
        int ni = ty + r * 8;
        float v = tile[tx][ni];
        __nv_bfloat16 h = __float2bfloat16_rn(v);
        size_t o = lw + (size_t)(n0 + ni) * K + k0 + tx;
        hi[o] = h;
        lo[o] = __float2bfloat16_rn(v - __bfloat162float(h));
    }
}

// ============================ mma.sync bf16x3 GEMM (templated tile-M) ============================
template<int EPI, int TM>  // EPI: 0 fp32 out; 2 bf16 hi/lo out; 3 GELU + bf16 hi/lo out
__global__ void __launch_bounds__(256) mma_gemm_kernel(
    const __nv_bfloat16* __restrict__ Ahi, const __nv_bfloat16* __restrict__ Alo,
    const __nv_bfloat16* __restrict__ Bhi, const __nv_bfloat16* __restrict__ Blo,
    const float* __restrict__ bias, float* __restrict__ C,
    __nv_bfloat16* __restrict__ Chi, __nv_bfloat16* __restrict__ Clo, int N, int K)
{
    constexpr int MBN   = TM / 64;
    constexpr int ABYTES = TM * 128;
    constexpr int STAGE  = 2 * ABYTES + 32768;
    extern __shared__ char smem[];
    const int tid  = threadIdx.x;
    const int lane = tid & 31;
    const int wid  = tid >> 5;
    const int m0 = blockIdx.y * TM, n0 = blockIdx.x * 128;
    const int wrow = (wid >> 1) * (16 * MBN);
    const int wcol = (wid & 1) * 64;
    const uint32_t sbase = smem_to_u32(smem);

    float acc[MBN][8][4];
    #pragma unroll
    for (int a = 0; a < MBN; a++)
        #pragma unroll
        for (int b = 0; b < 8; b++)
            #pragma unroll
            for (int c = 0; c < 4; c++) acc[a][b][c] = 0.f;

    const int nc = K >> 6;

    auto loadChunk = [&](int c) {
        uint32_t sb = sbase + (uint32_t)(c & 1) * STAGE;
        int k0 = c << 6;
        #pragma unroll
        for (int t2 = 0; t2 < 2; t2++) {
            const __nv_bfloat16* s = t2 ? Alo : Ahi;
            #pragma unroll
            for (int it = 0; it < TM / 32; it++) {
                int idx = it * 256 + tid;
                int row = idx >> 3, ch = idx & 7;
                CP_ASYNC16(sb + t2 * ABYTES + ASM_OFF(row, ch),
                           s + (size_t)(m0 + row) * K + k0 + ch * 8);
            }
        }
        #pragma unroll
        for (int t2 = 0; t2 < 2; t2++) {
            const __nv_bfloat16* s = t2 ? Blo : Bhi;
            #pragma unroll
            for (int it = 0; it < 4; it++) {
                int idx = it * 256 + tid;
                int row = idx >> 3, ch = idx & 7;
                CP_ASYNC16(sb + 2 * ABYTES + t2 * 16384 + ASM_OFF(row, ch),
                           s + (size_t)(n0 + row) * K + k0 + ch * 8);
            }
        }
        CP_COMMIT();
    };

    loadChunk(0);
    if (nc > 1) loadChunk(1);

    for (int c = 0; c < nc; c++) {
        if (c + 1 < nc) CP_WAIT1(); else CP_WAIT0();
        __syncthreads();
        uint32_t sb = sbase + (uint32_t)(c & 1) * STAGE;
        uint32_t sAh = sb, sAl = sb + ABYTES, sBh = sb + 2 * ABYTES, sBl = sb + 2 * ABYTES + 16384;
        #pragma unroll
        for (int ks = 0; ks < 4; ks++) {
            uint32_t ah[MBN][4], al[MBN][4], bh[4][4], bl[4][4];
            {
                int sub = lane >> 3;
                int row16 = (lane & 7) + ((sub & 1) << 3);
                int kc = ks * 2 + (sub >> 1);
                #pragma unroll
                for (int mb = 0; mb < MBN; mb++) {
                    int row = wrow + mb * 16 + row16;
                    uint32_t off = ASM_OFF(row, kc);
                    ldsm4(ah[mb], sAh + off);
                    ldsm4(al[mb], sAl + off);
                }
            }
            {
                int sub = lane >> 3;
                int kc = ks * 2 + (sub & 1);
                int nr = ((sub >> 1) << 3) + (lane & 7);
                #pragma unroll
                for (int j = 0; j < 4; j++) {
                    int row = wcol + j * 16 + nr;
                    uint32_t off = ASM_OFF(row, kc);
                    ldsm4(bh[j], sBh + off);
                    ldsm4(bl[j], sBl + off);
                }
            }
            #pragma unroll
            for (int mb = 0; mb < MBN; mb++)
                #pragma unroll
                for (int j = 0; j < 4; j++) {
                    mma16816(acc[mb][2*j],     ah[mb], &bh[j][0]);
                    mma16816(acc[mb][2*j],     ah[mb], &bl[j][0]);
                    mma16816(acc[mb][2*j],     al[mb], &bh[j][0]);
                    mma16816(acc[mb][2*j + 1], ah[mb], &bh[j][2]);
                    mma16816(acc[mb][2*j + 1], ah[mb], &bl[j][2]);
                    mma16816(acc[mb][2*j + 1], al[mb], &bh[j][2]);
                }
        }
        __syncthreads();
        if (c + 2 < nc) loadChunk(c + 2);
    }

    const int r_l = lane >> 2;
    const int c_l = (lane & 3) << 1;
    #pragma unroll
    for (int mb = 0; mb < MBN; mb++) {
        #pragma unroll
        for (int nb = 0; nb < 8; nb++) {
            int row = m0 + wrow + mb * 16 + r_l;
            int col = n0 + wcol + nb * 8 + c_l;
            float b0 = bias[col], b1 = bias[col + 1];
            float v0 = acc[mb][nb][0] + b0;
            float v1 = acc[mb][nb][1] + b1;
            float v2 = acc[mb][nb][2] + b0;
            float v3 = acc[mb][nb][3] + b1;
            if (EPI == 3) {
                v0 = 0.5f * v0 * (1.f + erff(v0 * 0.70710678118654752f));
                v1 = 0.5f * v1 * (1.f + erff(v1 * 0.70710678118654752f));
                v2 = 0.5f * v2 * (1.f + erff(v2 * 0.70710678118654752f));
                v3 = 0.5f * v3 * (1.f + erff(v3 * 0.70710678118654752f));
            }
            if (EPI == 0) {
                *reinterpret_cast<float2*>(C + (size_t)row * N + col)       = make_float2(v0, v1);
                *reinterpret_cast<float2*>(C + (size_t)(row + 8) * N + col) = make_float2(v2, v3);
            } else {
                __nv_bfloat162 h01 = __floats2bfloat162_rn(v0, v1);
                __nv_bfloat162 h23 = __floats2bfloat162_rn(v2, v3);
                __nv_bfloat162 l01 = __floats2bfloat162_rn(v0 - __bfloat162float(h01.x),
                                                           v1 - __bfloat162float(h01.y));
                __nv_bfloat162 l23 = __floats2bfloat162_rn(v2 - __bfloat162float(h23.x),
                                                           v3 - __bfloat162float(h23.y));
                *reinterpret_cast<__nv_bfloat162*>(Chi + (size_t)row * N + col)       = h01;
                *reinterpret_cast<__nv_bfloat162*>(Chi + (size_t)(row + 8) * N + col) = h23;
                *reinterpret_cast<__nv_bfloat162*>(Clo + (size_t)row * N + col)       = l01;
                *reinterpret_cast<__nv_bfloat162*>(Clo + (size_t)(row + 8) * N + col) = l23;
            }
        }
    }
}

// ============================ tensor-core attention (double-buffered K/V) ============================
// smem: QH 0..16K, QL 16K..32K, KV stages at 32K + s*32K (KH,KL,VH,VL 8K each), bias[2][64]
#define AT_QH   0
#define AT_QL   16384
#define AT_KV   32768
#define AT_BIAS 98304
#define AT_SMEM (98304 + 512)

__global__ void __launch_bounds__(128) attn_tc_kernel(
    const __nv_bfloat16* __restrict__ qh, const __nv_bfloat16* __restrict__ ql,
    const float* __restrict__ pep, float* __restrict__ part, float* __restrict__ plsum)
{
    extern __shared__ char sm[];
    const int h = blockIdx.y, sl = blockIdx.z;
    const int q0 = blockIdx.x * 128;
    const int tid = threadIdx.x, lane = tid & 31, wid = tid >> 5;
    const int wrow = wid * 32;
    const int sub = lane >> 3;
    const uint32_t sb = smem_to_u32(sm);
    float* bias = reinterpret_cast<float*>(sm + AT_BIAS);

    // Q tile + KV chunk 0 (one cp.async group)
    #pragma unroll
    for (int it = 0; it < 8; it++) {
        int idx = it * 128 + tid;
        int row = idx >> 3, ch = idx & 7;
        size_t g = (size_t)(q0 + row) * 1536 + h * 64 + ch * 8;
        uint32_t off = ASM_OFF(row, ch);
        CP_ASYNC16(sb + AT_QH + off, qh + g);
        CP_ASYNC16(sb + AT_QL + off, ql + g);
    }
    {
        const int kk = sl * 512;
        uint32_t stb = sb + AT_KV;
        #pragma unroll
        for (int it = 0; it < 4; it++) {
            int idx = it * 128 + tid;
            int row = idx >> 3, ch = idx & 7;
            size_t gk = (size_t)(kk + row) * 1536 + 512 + h * 64 + ch * 8;
            uint32_t off = ASM_OFF(row, ch);
            CP_ASYNC16(stb + off,         qh + gk);
            CP_ASYNC16(stb + 8192 + off,  ql + gk);
            CP_ASYNC16(stb + 16384 + off, qh + gk + 512);
            CP_ASYNC16(stb + 24576 + off, ql + gk + 512);
        }
        if (tid < 64) bias[tid] = pep[(size_t)(kk + tid) * HH + h];
    }
    CP_COMMIT();

    float O[2][8][4];
    float ls[2][2] = {{0.f, 0.f}, {0.f, 0.f}};
    #pragma unroll
    for (int mb = 0; mb < 2; mb++)
        #pragma unroll
        for (int nb = 0; nb < 8; nb++)
            #pragma unroll
            for (int u = 0; u < 4; u++) O[mb][nb][u] = 0.f;

    for (int c = 0; c < 8; c++) {
        CP_WAIT0();
        __syncthreads();
        // prefetch next chunk into the other stage (overlaps compute of chunk c)
        if (c < 7) {
            const int kn = sl * 512 + (c + 1) * 64;
            uint32_t stb = sb + AT_KV + (uint32_t)((c + 1) & 1) * 32768;
            #pragma unroll
            for (int it = 0; it < 4; it++) {
                int idx = it * 128 + tid;
                int row = idx >> 3, ch = idx & 7;
                size_t gk = (size_t)(kn + row) * 1536 + 512 + h * 64 + ch * 8;
                uint32_t off = ASM_OFF(row, ch);
                CP_ASYNC16(stb + off,         qh + gk);
                CP_ASYNC16(stb + 8192 + off,  ql + gk);
                CP_ASYNC16(stb + 16384 + off, qh + gk + 512);
                CP_ASYNC16(stb + 24576 + off, ql + gk + 512);
            }
            if (tid < 64) bias[((c + 1) & 1) * 64 + tid] = pep[(size_t)(kn + tid) * HH + h];
            CP_COMMIT();
        }
        const uint32_t stc = sb + AT_KV + (uint32_t)(c & 1) * 32768;
        const uint32_t sKH = stc, sKL = stc + 8192, sVH = stc + 16384, sVL = stc + 24576;
        const float* bs = bias + (c & 1) * 64;

        // ---- S = Q K^T (bf16 triple) ----
        float S[2][8][4];
        #pragma unroll
        for (int mb = 0; mb < 2; mb++)
            #pragma unroll
            for (int nb = 0; nb < 8; nb++)
                #pragma unroll
                for (int u = 0; u < 4; u++) S[mb][nb][u] = 0.f;
        #pragma unroll
        for (int kb = 0; kb < 4; kb++) {
            uint32_t ah[2][4], al[2][4];
            int r16 = (lane & 7) + ((sub & 1) << 3);
            int chA = kb * 2 + (sub >> 1);
            #pragma unroll
            for (int mb = 0; mb < 2; mb++) {
                int row = wrow + mb * 16 + r16;
                uint32_t off = ASM_OFF(row, chA);
                ldsm4(ah[mb], sb + AT_QH + off);
                ldsm4(al[mb], sb + AT_QL + off);
            }
            int chB = kb * 2 + (sub & 1);
            int nr = ((sub >> 1) << 3) + (lane & 7);
            #pragma unroll
            for (int j = 0; j < 4; j++) {
                uint32_t bh[4], bl[4];
                int row = j * 16 + nr;
                uint32_t off = ASM_OFF(row, chB);
                ldsm4(bh, sKH + off);
                ldsm4(bl, sKL + off);
                #pragma unroll
                for (int mb = 0; mb < 2; mb++) {
                    mma16816(S[mb][2*j],   ah[mb], &bh[0]);
                    mma16816(S[mb][2*j],   al[mb], &bh[0]);
                    mma16816(S[mb][2*j],   ah[mb], &bl[0]);
                    mma16816(S[mb][2*j+1], ah[mb], &bh[2]);
                    mma16816(S[mb][2*j+1], al[mb], &bh[2]);
                    mma16816(S[mb][2*j+1], ah[mb], &bl[2]);
                }
            }
        }

        // ---- softmax (fixed m=0) + in-register bf16 hi/lo pack of P ----
        uint32_t Ph[2][8][2], Pl[2][8][2];
        #pragma unroll
        for (int mb = 0; mb < 2; mb++)
            #pragma unroll
            for (int nb = 0; nb < 8; nb++) {
                int col = nb * 8 + ((lane & 3) << 1);
                float b0 = bs[col], b1 = bs[col + 1];
                float p0 = __expf(fmaf(S[mb][nb][0], 0.125f, -b0));
                float p1 = __expf(fmaf(S[mb][nb][1], 0.125f, -b1));
                float p2 = __expf(fmaf(S[mb][nb][2], 0.125f, -b0));
                float p3 = __expf(fmaf(S[mb][nb][3], 0.125f, -b1));
                ls[mb][0] += p0 + p1;
                ls[mb][1] += p2 + p3;
                __nv_bfloat162 h01 = __floats2bfloat162_rn(p0, p1);
                __nv_bfloat162 h23 = __floats2bfloat162_rn(p2, p3);
                __nv_bfloat162 l01 = __floats2bfloat162_rn(p0 - __bfloat162float(h01.x),
                                                           p1 - __bfloat162float(h01.y));
                __nv_bfloat162 l23 = __floats2bfloat162_rn(p2 - __bfloat162float(h23.x),
                                                           p3 - __bfloat162float(h23.y));
                Ph[mb][nb][0] = *reinterpret_cast<uint32_t*>(&h01);
                Ph[mb][nb][1] = *reinterpret_cast<uint32_t*>(&h23);
                Pl[mb][nb][0] = *reinterpret_cast<uint32_t*>(&l01);
                Pl[mb][nb][1] = *reinterpret_cast<uint32_t*>(&l23);
            }

        // ---- O += P V (triple) ----
        #pragma unroll
        for (int kb2 = 0; kb2 < 4; kb2++) {
            int krow = kb2 * 16 + ((sub & 1) << 3) + (lane & 7);
            #pragma unroll
            for (int dI = 0; dI < 4; dI++) {
                uint32_t vh[4], vl[4];
                int ch = dI * 2 + (sub >> 1);
                uint32_t off = ASM_OFF(krow, ch);
                ldsm4t(vh, sVH + off);
                ldsm4t(vl, sVL + off);
                #pragma unroll
                for (int mb = 0; mb < 2; mb++) {
                    uint32_t pa[4] = {Ph[mb][2*kb2][0], Ph[mb][2*kb2][1],
                                      Ph[mb][2*kb2+1][0], Ph[mb][2*kb2+1][1]};
                    uint32_t la[4] = {Pl[mb][2*kb2][0], Pl[mb][2*kb2][1],
                                      Pl[mb][2*kb2+1][0], Pl[mb][2*kb2+1][1]};
                    mma16816(O[mb][2*dI],   pa, &vh[0]);
                    mma16816(O[mb][2*dI],   la, &vh[0]);
                    mma16816(O[mb][2*dI],   pa, &vl[0]);
                    mma16816(O[mb][2*dI+1], pa, &vh[2]);
                    mma16816(O[mb][2*dI+1], la, &vh[2]);
                    mma16816(O[mb][2*dI+1], pa, &vl[2]);
                }
            }
        }
    }

    #pragma unroll
    for (int mb = 0; mb < 2; mb++)
        #pragma unroll
        for (int r = 0; r < 2; r++) {
            float v = ls[mb][r];
            v += __shfl_xor_sync(0xffffffffu, v, 1);
            v += __shfl_xor_sync(0xffffffffu, v, 2);
            ls[mb][r] = v;
        }
    const size_t base = (size_t)(sl * HH + h) * NN;
    #pragma unroll
    for (int mb = 0; mb < 2; mb++) {
        int rowA = q0 + wrow + mb * 16 + (lane >> 2);
        int rowB = rowA + 8;
        if ((lane & 3) == 0) {
            plsum[base + rowA] = ls[mb][0];
            plsum[base + rowB] = ls[mb][1];
        }
        #pragma unroll
        for (int nb = 0; nb < 8; nb++) {
            int col = nb * 8 + ((lane & 3) << 1);
            *reinterpret_cast<float2*>(part + (base + rowA) * 64 + col) = make_float2(O[mb][nb][0], O[mb][nb][1]);
            *reinterpret_cast<float2*>(part + (base + rowB) * 64 + col) = make_float2(O[mb][nb][2], O[mb][nb][3]);
        }
    }
}

__global__ void attn_combine_kernel(const float* __restrict__ part, const float* __restrict__ pls,
                                    __nv_bfloat16* __restrict__ ohi, __nv_bfloat16* __restrict__ olo) {
    int i = blockIdx.x, t = threadIdx.x;
    #pragma unroll
    for (int rep = 0; rep < 2; rep++) {
        int idx = t + rep * 256;
        int h = idx >> 6, d = idx & 63;
        float v = 0.f, l = 0.f;
        #pragma unroll
        for (int s = 0; s < 4; s++) {
            l += pls[(size_t)(s * HH + h) * NN + i];
            v += part[((size_t)(s * HH + h) * NN + i) * 64 + d];
        }
        float r = v / l;
        __nv_bfloat16 hb = __float2bfloat16_rn(r);
        ohi[(size_t)i * DD + idx] = hb;
        olo[(size_t)i * DD + idx] = __float2bfloat16_rn(r - __bfloat162float(hb));
    }
}

// ============================ LN (fp32 out + bf16 hi/lo) ============================
__global__ void ln_kernel(const float* __restrict__ a, const float* __restrict__ b,
                          const float* __restrict__ g, const float* __restrict__ be,
                          float* __restrict__ out,
                          __nv_bfloat16* __restrict__ ohi, __nv_bfloat16* __restrict__ olo) {
    __shared__ float sh[256];
    __shared__ float s_mu, s_r;
    int i = blockIdx.x, t = threadIdx.x;
    float v0 = a[(size_t)i * DD + t]       + b[(size_t)i * DD + t];
    float v1 = a[(size_t)i * DD + 256 + t] + b[(size_t)i * DD + 256 + t];
    sh[t] = v0 + v1; __syncthreads();
    for (int k = 128; k > 0; k >>= 1) { if (t < k) sh[t] += sh[t + k]; __syncthreads(); }
    if (t == 0) s_mu = sh[0] * (1.f / DD);
    __syncthreads();
    float mu = s_mu;
    float d0 = v0 - mu, d1 = v1 - mu;
    sh[t] = d0 * d0 + d1 * d1; __syncthreads();
    for (int k = 128; k > 0; k >>= 1) { if (t < k) sh[t] += sh[t + k]; __syncthreads(); }
    if (t == 0) s_r = rsqrtf(sh[0] * (1.f / DD) + 1e-5f);
    __syncthreads();
    float r = s_r;
    float o0 = d0 * r * g[t]       + be[t];
    float o1 = d1 * r * g[256 + t] + be[256 + t];
    out[(size_t)i * DD + t]       = o0;
    out[(size_t)i * DD + 256 + t] = o1;
    __nv_bfloat16 h0 = __float2bfloat16_rn(o0);
    __nv_bfloat16 h1 = __float2bfloat16_rn(o1);
    ohi[(size_t)i * DD + t]       = h0;
    ohi[(size_t)i * DD + 256 + t] = h1;
    olo[(size_t)i * DD + t]       = __float2bfloat16_rn(o0 - __bfloat162float(h0));
    olo[(size_t)i * DD + 256 + t] = __float2bfloat16_rn(o1 - __bfloat162float(h1));
}

// ============================ launch ============================
extern "C" void kernel_launch(void* const* d_in, const int* in_sizes, int n_in,
                              void* d_out, int out_size) {
    const float* node_features = (const float*)d_in[0];
    const int*   edge_index    = (const int*)  d_in[1];
    const float* pe_proj_W     = (const float*)d_in[2];
    const float* pe_proj_b     = (const float*)d_in[3];
    const float* qkv_W         = (const float*)d_in[4];
    const float* qkv_b         = (const float*)d_in[5];
    const float* peb_W         = (const float*)d_in[6];
    const float* peb_b         = (const float*)d_in[7];
    const float* out_W         = (const float*)d_in[8];
    const float* out_b         = (const float*)d_in[9];
    const float* ffn_W1        = (const float*)d_in[10];
    const float* ffn_b1        = (const float*)d_in[11];
    const float* ffn_W2        = (const float*)d_in[12];
    const float* ffn_b2        = (const float*)d_in[13];
    const float* ln1_g         = (const float*)d_in[14];
    const float* ln1_b         = (const float*)d_in[15];
    const float* ln2_g         = (const float*)d_in[16];
    const float* ln2_b         = (const float*)d_in[17];
    float* outp = (float*)d_out;

    float *x_, *x1_, *o_, *pep_, *part_, *pls_;
    __nv_bfloat16 *Ahi_, *Alo_, *Hhi_, *Hlo_, *Qh_, *Ql_, *T2b_, *T3b_, *T4b_;
    __nv_bfloat16 *qWh_, *qWl_, *oWh_, *oWl_, *f1h_, *f1l_, *f2h_, *f2l_;
    cudaGetSymbolAddress((void**)&x_,   g_x);
    cudaGetSymbolAddress((void**)&x1_,  g_x1);
    cudaGetSymbolAddress((void**)&o_,   g_o);
    cudaGetSymbolAddress((void**)&pep_, g_pep);
    cudaGetSymbolAddress((void**)&part_,g_part);
    cudaGetSymbolAddress((void**)&pls_, g_plsum);
    cudaGetSymbolAddress((void**)&Ahi_, g_Ahi);
    cudaGetSymbolAddress((void**)&Alo_, g_Alo);
    cudaGetSymbolAddress((void**)&Hhi_, g_Hhi);
    cudaGetSymbolAddress((void**)&Hlo_, g_Hlo);
    cudaGetSymbolAddress((void**)&Qh_,  g_QKVhi);
    cudaGetSymbolAddress((void**)&Ql_,  g_QKVlo);
    cudaGetSymbolAddress((void**)&T2b_, g_T2b);
    cudaGetSymbolAddress((void**)&T3b_, g_T3b);
    cudaGetSymbolAddress((void**)&T4b_, g_T4b);
    cudaGetSymbolAddress((void**)&qWh_, g_qkvW_hi);
    cudaGetSymbolAddress((void**)&qWl_, g_qkvW_lo);
    cudaGetSymbolAddress((void**)&oWh_, g_outW_hi);
    cudaGetSymbolAddress((void**)&oWl_, g_outW_lo);
    cudaGetSymbolAddress((void**)&f1h_, g_f1W_hi);
    cudaGetSymbolAddress((void**)&f1l_, g_f1W_lo);
    cudaGetSymbolAddress((void**)&f2h_, g_f2W_hi);
    cudaGetSymbolAddress((void**)&f2l_, g_f2W_lo);

    constexpr int GS128 = 2 * (2 * 128 * 128 + 32768);
    constexpr int GS64  = 2 * (2 * 64  * 128 + 32768);
    cudaFuncSetAttribute(mma_gemm_kernel<2,128>, cudaFuncAttributeMaxDynamicSharedMemorySize, GS128);
    cudaFuncSetAttribute(mma_gemm_kernel<3,128>, cudaFuncAttributeMaxDynamicSharedMemorySize, GS128);
    cudaFuncSetAttribute(mma_gemm_kernel<0,64>,  cudaFuncAttributeMaxDynamicSharedMemorySize, GS64);
    cudaFuncSetAttribute(attn_tc_kernel, cudaFuncAttributeMaxDynamicSharedMemorySize, AT_SMEM);

    // side stream + events: created once (resource setup, identical work every call)
    static cudaStream_t s_side = nullptr;
    static cudaEvent_t  ev_fork = nullptr, ev_pe = nullptr;
    if (s_side == nullptr) {
        cudaStreamCreateWithFlags(&s_side, cudaStreamNonBlocking);
        cudaEventCreateWithFlags(&ev_fork, cudaEventDisableTiming);
        cudaEventCreateWithFlags(&ev_pe,   cudaEventDisableTiming);
    }

    // ---- fork: PE pipeline on side stream (disjoint buffers from main-path work) ----
    cudaEventRecord(ev_fork, 0);
    cudaStreamWaitEvent(s_side, ev_fork, 0);
    zero_bm_kernel<<<(NN*64)/256, 256, 0, s_side>>>();
    scatter_bm_kernel<<<EEC/256, 256, 0, s_side>>>(edge_index);
    build_bm_kernel<<<NN, 64, 0, s_side>>>();
    t2_kernel<<<NN, 256, 0, s_side>>>();
    spmm_bf_kernel<<<NN, 256, 0, s_side>>>(T2b_, T3b_);
    spmm_bf_kernel<<<NN, 256, 0, s_side>>>(T3b_, T4b_);
    diag2_kernel<<<NN, 256, 0, s_side>>>();
    pe_kernel<<<(NN + 127) / 128, 128, 0, s_side>>>(pe_proj_W, pe_proj_b);
    pep_kernel<<<(NN + 127) / 128, 128, 0, s_side>>>(peb_W, peb_b);
    cudaEventRecord(ev_pe, s_side);

    // ---- main stream: weight conversion + transformer ----
    convW_kernel<<<dim3(1536/32, 512/32, LLC),  dim3(32,8)>>>(qkv_W,  qWh_, qWl_, DD,  3*DD);
    convW_kernel<<<dim3(512/32,  512/32, LLC),  dim3(32,8)>>>(out_W,  oWh_, oWl_, DD,  DD);
    convW_kernel<<<dim3(2048/32, 512/32, LLC),  dim3(32,8)>>>(ffn_W1, f1h_, f1l_, DD,  DFFC);
    convW_kernel<<<dim3(512/32,  2048/32, LLC), dim3(32,8)>>>(ffn_W2, f2h_, f2l_, DFFC, DD);
    split_copy_kernel<<<(NN*DD)/256, 256>>>(node_features);

    for (int l = 0; l < LLC; l++) {
        mma_gemm_kernel<2,128><<<dim3(1536/128, NN/128), 256, GS128>>>(
            Ahi_, Alo_, qWh_ + (size_t)l*3*DD*DD, qWl_ + (size_t)l*3*DD*DD,
            qkv_b + (size_t)l*3*DD, nullptr, Qh_, Ql_, 3*DD, DD);
        if (l == 0) cudaStreamWaitEvent(0, ev_pe, 0);   // join: attention needs pep
        attn_tc_kernel<<<dim3(NN/128, HH, 4), 128, AT_SMEM>>>(Qh_, Ql_, pep_ + (size_t)l*NN*HH, part_, pls_);
        attn_combine_kernel<<<NN, 256>>>(part_, pls_, Ahi_, Alo_);
        mma_gemm_kernel<0,64><<<dim3(DD/128, NN/64), 256, GS64>>>(
            Ahi_, Alo_, oWh_ + (size_t)l*DD*DD, oWl_ + (size_t)l*DD*DD,
            out_b + (size_t)l*DD, o_, nullptr, nullptr, DD, DD);
        ln_kernel<<<NN, 256>>>(x_, o_, ln1_g + (size_t)l*DD, ln1_b + (size_t)l*DD, x1_, Ahi_, Alo_);
        mma_gemm_kernel<3,128><<<dim3(DFFC/128, NN/128), 256, GS128>>>(
            Ahi_, Alo_, f1h_ + (size_t)l*DD*DFFC, f1l_ + (size_t)l*DD*DFFC,
            ffn_b1 + (size_t)l*DFFC, nullptr, Hhi_, Hlo_, DFFC, DD);
        mma_gemm_kernel<0,64><<<dim3(DD/128, NN/64), 256, GS64>>>(
            Hhi_, Hlo_, f2h_ + (size_t)l*DFFC*DD, f2l_ + (size_t)l*DFFC*DD,
            ffn_b2 + (size_t)l*DD, o_, nullptr, nullptr, DD, DFFC);
        float* xout = (l == LLC - 1) ? outp : x_;
        ln_kernel<<<NN, 256>>>(x1_, o_, ln2_g + (size_t)l*DD, ln2_b + (size_t)l*DD, xout, Ahi_, Alo_);
    }
}